// round 2
// baseline (speedup 1.0000x reference)
#include <cuda_runtime.h>
#include <cuda_bf16.h>
#include <math.h>

// ---------------------------------------------------------------------------
// Problem constants
// ---------------------------------------------------------------------------
#define S_   1024
#define HD_  2048
#define L_   2
#define G_   4
#define D_   64
#define GS_  8
#define GD_  (G_ * D_)       // 256
#define FF_  8192
#define V_   38400

// ---------------------------------------------------------------------------
// Scratch (device globals -- no allocation allowed)
// ---------------------------------------------------------------------------
__device__ float g_Wq_r[L_ * HD_ * GD_];    // 4 MB  reduced Wq (cols summed over j)
__device__ float g_bq_r[L_ * GD_];
__device__ float g_Wo_r[L_ * GD_ * HD_];    // 4 MB  reduced Wo (rows summed over j)
__device__ float g_h   [S_ * HD_];          // 8 MB  activations
__device__ float g_t2  [S_ * HD_];          // 8 MB  attn_out / ffn_out / final-LN
__device__ float g_a1  [S_ * FF_];          // 32 MB ffn hidden
__device__ float g_qr  [S_ * GD_];
__device__ float g_k   [S_ * GD_];
__device__ float g_kt  [GD_ * S_];          // K^T per (g,d)
__device__ float g_v   [S_ * GD_];
__device__ float g_ctx [S_ * GD_];
__device__ float g_sc  [G_ * S_ * S_];      // 16 MB scores

// ---------------------------------------------------------------------------
// Generic batched SGEMM:  C = alpha * A(MxK) * B(KxN) [+ bias] [relu]
// 128x128 block, 16 K-tile, 8x8 per-thread micro-tile, 256 threads.
// M assumed multiple of 128 here (M = 1024 always); N, arbitrary w/ guards;
// K multiple of 16 (all our K: 64,256,1024,2048,8192).
// ---------------------------------------------------------------------------
__global__ __launch_bounds__(256) void sgemm_kernel(
    int M, int N, int K, float alpha,
    const float* __restrict__ A, int lda, long long sA,
    const float* __restrict__ B, int ldb, long long sB,
    const float* __restrict__ bias,
    float* __restrict__ C, int ldc, long long sC,
    int relu)
{
    const int BM = 128, BN = 128, BK = 16;
    __shared__ float As[BK][BM];
    __shared__ float Bs[BK][BN];

    long long bz = blockIdx.z;
    A += bz * sA;
    B += bz * sB;
    C += bz * sC;

    int row0 = blockIdx.y * BM;
    int col0 = blockIdx.x * BN;
    int tid  = threadIdx.x;
    int tr   = tid >> 4;       // 0..15
    int tc   = tid & 15;       // 0..15

    // A tile loader: 128 rows x 16 cols, float4 per load, 2 passes
    int arow = tid >> 2;               // 0..63
    int acol = (tid & 3) * 4;          // 0,4,8,12
    // B tile loader: 16 rows x 128 cols
    int brow = tid >> 5;               // 0..7
    int bcol = (tid & 31) * 4;         // 0..124

    float acc[8][8];
#pragma unroll
    for (int i = 0; i < 8; i++)
#pragma unroll
        for (int j = 0; j < 8; j++) acc[i][j] = 0.f;

    for (int k0 = 0; k0 < K; k0 += BK) {
#pragma unroll
        for (int i = 0; i < 2; i++) {
            int m = row0 + arow + i * 64;
            int k = k0 + acol;
            float4 v = make_float4(0.f, 0.f, 0.f, 0.f);
            if (m < M)
                v = *(const float4*)(A + (long long)m * lda + k);
            As[acol + 0][arow + i * 64] = v.x;
            As[acol + 1][arow + i * 64] = v.y;
            As[acol + 2][arow + i * 64] = v.z;
            As[acol + 3][arow + i * 64] = v.w;
        }
#pragma unroll
        for (int i = 0; i < 2; i++) {
            int k = k0 + brow + i * 8;
            int n = col0 + bcol;
            float4 v = make_float4(0.f, 0.f, 0.f, 0.f);
            if (n < N)
                v = *(const float4*)(B + (long long)k * ldb + n);
            *(float4*)&Bs[brow + i * 8][bcol] = v;
        }
        __syncthreads();

#pragma unroll
        for (int kk = 0; kk < BK; kk++) {
            float ra[8], rb[8];
#pragma unroll
            for (int i = 0; i < 8; i++) ra[i] = As[kk][tr * 8 + i];
#pragma unroll
            for (int j = 0; j < 8; j++) rb[j] = Bs[kk][tc * 8 + j];
#pragma unroll
            for (int i = 0; i < 8; i++)
#pragma unroll
                for (int j = 0; j < 8; j++)
                    acc[i][j] += ra[i] * rb[j];
        }
        __syncthreads();
    }

#pragma unroll
    for (int i = 0; i < 8; i++) {
        int m = row0 + tr * 8 + i;
        if (m >= M) continue;
#pragma unroll
        for (int j = 0; j < 8; j++) {
            int n = col0 + tc * 8 + j;
            if (n >= N) continue;
            float v = alpha * acc[i][j];
            if (bias) v += bias[n];
            if (relu) v = fmaxf(v, 0.f);
            C[(long long)m * ldc + n] = v;
        }
    }
}

// ---------------------------------------------------------------------------
// Softmax over rows of length T (one block per row)
// ---------------------------------------------------------------------------
__global__ __launch_bounds__(256) void softmax_kernel(float* __restrict__ Srows, int T)
{
    float* row = Srows + (long long)blockIdx.x * T;
    __shared__ float red[256];
    int tid = threadIdx.x;

    float m = -INFINITY;
    for (int i = tid; i < T; i += 256) m = fmaxf(m, row[i]);
    red[tid] = m; __syncthreads();
    for (int s = 128; s > 0; s >>= 1) {
        if (tid < s) red[tid] = fmaxf(red[tid], red[tid + s]);
        __syncthreads();
    }
    m = red[0]; __syncthreads();

    float sum = 0.f;
    for (int i = tid; i < T; i += 256) {
        float e = expf(row[i] - m);
        row[i] = e;
        sum += e;
    }
    red[tid] = sum; __syncthreads();
    for (int s = 128; s > 0; s >>= 1) {
        if (tid < s) red[tid] += red[tid + s];
        __syncthreads();
    }
    float inv = 1.f / red[0];
    for (int i = tid; i < T; i += 256) row[i] *= inv;
}

// ---------------------------------------------------------------------------
// LayerNorm with optional residual: O = LN(X + R) * g + b   (N = 2048)
// one block (256 thr) per row, 8 elems/thread
// ---------------------------------------------------------------------------
__global__ __launch_bounds__(256) void ln_kernel(
    const float* __restrict__ X, const float* __restrict__ R,
    const float* __restrict__ g, const float* __restrict__ b,
    float* __restrict__ O)
{
    long long off = (long long)blockIdx.x * HD_;
    __shared__ float red[256];
    int tid = threadIdx.x;

    float xv[8];
    float lsum = 0.f;
#pragma unroll
    for (int i = 0; i < 8; i++) {
        int c = tid + i * 256;
        float x = X[off + c];
        if (R) x += R[off + c];
        xv[i] = x;
        lsum += x;
    }
    red[tid] = lsum; __syncthreads();
    for (int s = 128; s > 0; s >>= 1) {
        if (tid < s) red[tid] += red[tid + s];
        __syncthreads();
    }
    float mean = red[0] * (1.f / HD_);
    __syncthreads();

    float lvar = 0.f;
#pragma unroll
    for (int i = 0; i < 8; i++) {
        float d = xv[i] - mean;
        lvar += d * d;
    }
    red[tid] = lvar; __syncthreads();
    for (int s = 128; s > 0; s >>= 1) {
        if (tid < s) red[tid] += red[tid + s];
        __syncthreads();
    }
    float inv = rsqrtf(red[0] * (1.f / HD_) + 1e-5f);

#pragma unroll
    for (int i = 0; i < 8; i++) {
        int c = tid + i * 256;
        O[off + c] = (xv[i] - mean) * inv * g[c] + b[c];
    }
}

// ---------------------------------------------------------------------------
// Embedding gather: h[s,c] = tok[ids[s],c] + pos[s,c]
// ---------------------------------------------------------------------------
__global__ __launch_bounds__(256) void embed_kernel(
    const int* __restrict__ ids, const float* __restrict__ tok,
    const float* __restrict__ pos, float* __restrict__ h)
{
    long long idx = (long long)blockIdx.x * 256 + threadIdx.x;  // S*HD
    int c = (int)(idx & (HD_ - 1));
    int s = (int)(idx >> 11);
    h[idx] = tok[(long long)ids[s] * HD_ + c] + pos[idx];
}

// ---------------------------------------------------------------------------
// Weight pre-reductions (sum over sub-head axis j)
// ---------------------------------------------------------------------------
__global__ __launch_bounds__(256) void reduce_wq_kernel(
    const float* __restrict__ Wq, float* __restrict__ Wq_r)
{
    long long idx = (long long)blockIdx.x * 256 + threadIdx.x;  // L*HD*GD
    int gd = (int)(idx & (GD_ - 1));
    int k  = (int)((idx >> 8) & (HD_ - 1));
    int l  = (int)(idx >> 19);
    int gg = gd >> 6, d = gd & 63;
    const float* row = Wq + (((long long)l * HD_ + k) * HD_) + gg * (GS_ * D_) + d;
    float s = 0.f;
#pragma unroll
    for (int j = 0; j < GS_; j++) s += row[j * D_];
    Wq_r[idx] = s;
}

__global__ __launch_bounds__(256) void reduce_bq_kernel(
    const float* __restrict__ bq, float* __restrict__ bq_r)
{
    int idx = blockIdx.x * 256 + threadIdx.x;  // L*GD = 512
    if (idx >= L_ * GD_) return;
    int gd = idx & (GD_ - 1);
    int l  = idx >> 8;
    int gg = gd >> 6, d = gd & 63;
    const float* row = bq + (long long)l * HD_ + gg * (GS_ * D_) + d;
    float s = 0.f;
#pragma unroll
    for (int j = 0; j < GS_; j++) s += row[j * D_];
    bq_r[idx] = s;
}

__global__ __launch_bounds__(256) void reduce_wo_kernel(
    const float* __restrict__ Wo, float* __restrict__ Wo_r)
{
    long long idx = (long long)blockIdx.x * 256 + threadIdx.x;  // L*GD*HD
    int n  = (int)(idx & (HD_ - 1));
    int gd = (int)((idx >> 11) & (GD_ - 1));
    int l  = (int)(idx >> 19);
    int gg = gd >> 6, d = gd & 63;
    float s = 0.f;
#pragma unroll
    for (int j = 0; j < GS_; j++)
        s += Wo[(((long long)l * HD_) + gg * (GS_ * D_) + j * D_ + d) * HD_ + n];
    Wo_r[idx] = s;
}

// K transpose: Kt[gd, t] = K[t, gd]
__global__ __launch_bounds__(256) void transpose_k_kernel(
    const float* __restrict__ Kk, float* __restrict__ Kt)
{
    long long idx = (long long)blockIdx.x * 256 + threadIdx.x;  // GD*S
    int t  = (int)(idx & (S_ - 1));
    int gd = (int)(idx >> 10);
    Kt[idx] = Kk[(long long)t * GD_ + gd];
}

// ---------------------------------------------------------------------------
// Host orchestration
// ---------------------------------------------------------------------------
static void launch_gemm(int M, int N, int K, float alpha,
                        const float* A, int lda, long long sA,
                        const float* B, int ldb, long long sB,
                        const float* bias,
                        float* C, int ldc, long long sC,
                        int batch, int relu)
{
    dim3 grid((N + 127) / 128, (M + 127) / 128, batch);
    sgemm_kernel<<<grid, 256>>>(M, N, K, alpha, A, lda, sA, B, ldb, sB,
                                bias, C, ldc, sC, relu);
}

extern "C" void kernel_launch(void* const* d_in, const int* in_sizes, int n_in,
                              void* d_out, int out_size)
{
    const int*   ids     = (const int*)  d_in[0];
    const float* tok_emb = (const float*)d_in[1];
    const float* pos_emb = (const float*)d_in[2];
    const float* Wq      = (const float*)d_in[3];
    const float* bq      = (const float*)d_in[4];
    const float* Wk      = (const float*)d_in[5];
    const float* bk      = (const float*)d_in[6];
    const float* Wv      = (const float*)d_in[7];
    const float* bv      = (const float*)d_in[8];
    const float* Wo      = (const float*)d_in[9];
    const float* bo      = (const float*)d_in[10];
    const float* g1      = (const float*)d_in[11];
    const float* be1     = (const float*)d_in[12];
    const float* W1      = (const float*)d_in[13];
    const float* b1      = (const float*)d_in[14];
    const float* W2      = (const float*)d_in[15];
    const float* b2      = (const float*)d_in[16];
    const float* g2      = (const float*)d_in[17];
    const float* be2     = (const float*)d_in[18];
    const float* lnf_g   = (const float*)d_in[19];
    const float* lnf_b   = (const float*)d_in[20];
    const float* Whead   = (const float*)d_in[21];
    float* out = (float*)d_out;

    float *Wq_r, *bq_r, *Wo_r, *h, *t2, *a1, *qr, *kk, *kt, *vv, *ctx, *sc;
    cudaGetSymbolAddress((void**)&Wq_r, g_Wq_r);
    cudaGetSymbolAddress((void**)&bq_r, g_bq_r);
    cudaGetSymbolAddress((void**)&Wo_r, g_Wo_r);
    cudaGetSymbolAddress((void**)&h,    g_h);
    cudaGetSymbolAddress((void**)&t2,   g_t2);
    cudaGetSymbolAddress((void**)&a1,   g_a1);
    cudaGetSymbolAddress((void**)&qr,   g_qr);
    cudaGetSymbolAddress((void**)&kk,   g_k);
    cudaGetSymbolAddress((void**)&kt,   g_kt);
    cudaGetSymbolAddress((void**)&vv,   g_v);
    cudaGetSymbolAddress((void**)&ctx,  g_ctx);
    cudaGetSymbolAddress((void**)&sc,   g_sc);

    // --- weight pre-reductions (sum over sub-head axis j) ---
    reduce_wq_kernel<<<(L_ * HD_ * GD_) / 256, 256>>>(Wq, Wq_r);
    reduce_bq_kernel<<<2, 256>>>(bq, bq_r);
    reduce_wo_kernel<<<(L_ * GD_ * HD_) / 256, 256>>>(Wo, Wo_r);

    // --- embedding ---
    embed_kernel<<<(S_ * HD_) / 256, 256>>>(ids, tok_emb, pos_emb, h);

    for (int l = 0; l < L_; l++) {
        const float* Wq_l = Wq_r + (long long)l * HD_ * GD_;
        const float* bq_l = bq_r + (long long)l * GD_;
        const float* Wk_l = Wk   + (long long)l * HD_ * GD_;
        const float* bk_l = bk   + (long long)l * GD_;
        const float* Wv_l = Wv   + (long long)l * HD_ * GD_;
        const float* bv_l = bv   + (long long)l * GD_;
        const float* Wo_l = Wo_r + (long long)l * GD_ * HD_;
        const float* bo_l = bo   + (long long)l * HD_;
        const float* W1_l = W1   + (long long)l * HD_ * FF_;
        const float* b1_l = b1   + (long long)l * FF_;
        const float* W2_l = W2   + (long long)l * FF_ * HD_;
        const float* b2_l = b2   + (long long)l * HD_;

        // Q-sum / K / V projections  [S,HD] @ [HD,GD]
        launch_gemm(S_, GD_, HD_, 1.f, h, HD_, 0, Wq_l, GD_, 0, bq_l, qr, GD_, 0, 1, 0);
        launch_gemm(S_, GD_, HD_, 1.f, h, HD_, 0, Wk_l, GD_, 0, bk_l, kk, GD_, 0, 1, 0);
        launch_gemm(S_, GD_, HD_, 1.f, h, HD_, 0, Wv_l, GD_, 0, bv_l, vv, GD_, 0, 1, 0);

        // K transpose for NN scores GEMM
        transpose_k_kernel<<<(GD_ * S_) / 256, 256>>>(kk, kt);

        // scores[g] = (1/8) * Qsum_g @ K_g^T   (batch over groups)
        launch_gemm(S_, S_, D_, 0.125f,
                    qr, GD_, D_,
                    kt, S_, (long long)D_ * S_,
                    nullptr,
                    sc, S_, (long long)S_ * S_,
                    G_, 0);

        // softmax over last axis
        softmax_kernel<<<G_ * S_, 256>>>(sc, S_);

        // ctx[g] = attn_g @ V_g
        launch_gemm(S_, D_, S_, 1.f,
                    sc, S_, (long long)S_ * S_,
                    vv, GD_, D_,
                    nullptr,
                    ctx, GD_, D_,
                    G_, 0);

        // attn_out = ctx @ Wo_r + bo ; h = LN(h + attn_out)
        launch_gemm(S_, HD_, GD_, 1.f, ctx, GD_, 0, Wo_l, HD_, 0, bo_l, t2, HD_, 0, 1, 0);
        ln_kernel<<<S_, 256>>>(h, t2, g1 + (long long)l * HD_, be1 + (long long)l * HD_, h);

        // FFN
        launch_gemm(S_, FF_, HD_, 1.f, h, HD_, 0, W1_l, FF_, 0, b1_l, a1, FF_, 0, 1, 1);
        launch_gemm(S_, HD_, FF_, 1.f, a1, FF_, 0, W2_l, HD_, 0, b2_l, t2, HD_, 0, 1, 0);
        ln_kernel<<<S_, 256>>>(h, t2, g2 + (long long)l * HD_, be2 + (long long)l * HD_, h);
    }

    // final LN + lm head
    ln_kernel<<<S_, 256>>>(h, nullptr, lnf_g, lnf_b, t2);
    launch_gemm(S_, V_, HD_, 1.f, t2, HD_, 0, Whead, V_, 0, nullptr, out, V_, 0, 1, 0);
}

// round 3
// speedup vs baseline: 2.4307x; 2.4307x over previous
#include <cuda_runtime.h>
#include <cuda_bf16.h>
#include <math.h>
#include <stdint.h>

// ---------------------------------------------------------------------------
// Problem constants
// ---------------------------------------------------------------------------
#define S_   1024
#define HD_  2048
#define L_   2
#define G_   4
#define D_   64
#define GS_  8
#define GD_  (G_ * D_)       // 256
#define FF_  8192
#define V_   38400

// ---------------------------------------------------------------------------
// Scratch (device globals -- no allocation allowed)
// ---------------------------------------------------------------------------
__device__ float g_Wq_r[L_ * HD_ * GD_];
__device__ float g_bq_r[L_ * GD_];
__device__ float g_Wo_r[L_ * GD_ * HD_];
__device__ float g_h   [S_ * HD_];
__device__ float g_t2  [S_ * HD_];
__device__ float g_a1  [S_ * FF_];
__device__ float g_qr  [S_ * GD_];
__device__ float g_k   [S_ * GD_];
__device__ float g_kt  [GD_ * S_];
__device__ float g_v   [S_ * GD_];
__device__ float g_ctx [S_ * GD_];
__device__ float g_sc  [G_ * S_ * S_];

// ---------------------------------------------------------------------------
// tf32 helpers
// ---------------------------------------------------------------------------
__device__ __forceinline__ uint32_t f2tf32(float f) {
    uint32_t r;
    asm("cvt.rna.tf32.f32 %0, %1;" : "=r"(r) : "f"(f));
    return r;
}

__device__ __forceinline__ void mma_tf32(float c[4], const uint32_t a[4], const uint32_t b[2]) {
    asm volatile(
        "mma.sync.aligned.m16n8k8.row.col.f32.tf32.tf32.f32 "
        "{%0,%1,%2,%3}, {%4,%5,%6,%7}, {%8,%9}, {%0,%1,%2,%3};"
        : "+f"(c[0]), "+f"(c[1]), "+f"(c[2]), "+f"(c[3])
        : "r"(a[0]), "r"(a[1]), "r"(a[2]), "r"(a[3]),
          "r"(b[0]), "r"(b[1]));
}

// ---------------------------------------------------------------------------
// Batched tf32 tensor-core GEMM:  C = alpha * A(MxK) * B(KxN) [+bias][relu]
// 128x128x32 block, 8 warps (4 x 2), warp tile 32x64 (2x8 m16n8k8 frags).
// M multiple of 128 (always 1024 here). K multiple of 32. N arbitrary (guarded).
// ---------------------------------------------------------------------------
#define BM 128
#define BN 128
#define BKT 32
#define AP 132   // smem pitch (words) for As rows -- breaks bank aliasing
#define BP 132

__global__ __launch_bounds__(256) void tgemm_kernel(
    int M, int N, int K, float alpha,
    const float* __restrict__ A, int lda, long long sA,
    const float* __restrict__ B, int ldb, long long sB,
    const float* __restrict__ bias,
    float* __restrict__ C, int ldc, long long sC,
    int relu)
{
    __shared__ uint32_t As[BKT][AP];   // k-major: As[k][m]
    __shared__ uint32_t Bs[BKT][BP];   // k-major: Bs[k][n]

    long long bz = blockIdx.z;
    A += bz * sA;
    B += bz * sB;
    C += bz * sC;

    const int row0 = blockIdx.y * BM;
    const int col0 = blockIdx.x * BN;
    const int tid  = threadIdx.x;
    const int lane = tid & 31;
    const int warp = tid >> 5;
    const int wm   = (warp & 3) * 32;   // warp M offset inside block
    const int wn   = (warp >> 2) * 64;  // warp N offset inside block
    const int gid  = lane >> 2;         // 0..7
    const int tg   = lane & 3;          // 0..3

    // global loaders
    const int a_row = tid >> 3;          // 0..31 (m within pass; 4 passes of +32)
    const int a_col = (tid & 7) * 4;     // k
    const int b_row = tid >> 5;          // 0..7  (k within pass; 4 passes of +8)
    const int b_col = (tid & 31) * 4;    // n

    float4 ra[4], rb[4];

    // prefetch first tile
    {
#pragma unroll
        for (int p = 0; p < 4; p++) {
            int m = row0 + a_row + p * 32;
            ra[p] = *(const float4*)(A + (long long)m * lda + a_col);
        }
#pragma unroll
        for (int p = 0; p < 4; p++) {
            int k = b_row + p * 8;
            int n = col0 + b_col;
            rb[p] = (n < N) ? *(const float4*)(B + (long long)k * ldb + n)
                            : make_float4(0.f, 0.f, 0.f, 0.f);
        }
    }

    float acc[2][8][4];
#pragma unroll
    for (int mi = 0; mi < 2; mi++)
#pragma unroll
        for (int ni = 0; ni < 8; ni++)
#pragma unroll
            for (int c = 0; c < 4; c++) acc[mi][ni][c] = 0.f;

    for (int k0 = 0; k0 < K; k0 += BKT) {
        // store prefetched tile to smem (with tf32 rounding)
#pragma unroll
        for (int p = 0; p < 4; p++) {
            int m = a_row + p * 32;
            As[a_col + 0][m] = f2tf32(ra[p].x);
            As[a_col + 1][m] = f2tf32(ra[p].y);
            As[a_col + 2][m] = f2tf32(ra[p].z);
            As[a_col + 3][m] = f2tf32(ra[p].w);
        }
#pragma unroll
        for (int p = 0; p < 4; p++) {
            int k = b_row + p * 8;
            Bs[k][b_col + 0] = f2tf32(rb[p].x);
            Bs[k][b_col + 1] = f2tf32(rb[p].y);
            Bs[k][b_col + 2] = f2tf32(rb[p].z);
            Bs[k][b_col + 3] = f2tf32(rb[p].w);
        }
        __syncthreads();

        // prefetch next tile
        if (k0 + BKT < K) {
#pragma unroll
            for (int p = 0; p < 4; p++) {
                int m = row0 + a_row + p * 32;
                ra[p] = *(const float4*)(A + (long long)m * lda + (k0 + BKT) + a_col);
            }
#pragma unroll
            for (int p = 0; p < 4; p++) {
                int k = k0 + BKT + b_row + p * 8;
                int n = col0 + b_col;
                rb[p] = (n < N) ? *(const float4*)(B + (long long)k * ldb + n)
                                : make_float4(0.f, 0.f, 0.f, 0.f);
            }
        }

        // compute: 4 k-slices of 8
#pragma unroll
        for (int ks = 0; ks < 4; ks++) {
            const int k = ks * 8 + tg;
            uint32_t afr[2][4];
#pragma unroll
            for (int mi = 0; mi < 2; mi++) {
                int m = wm + mi * 16 + gid;
                afr[mi][0] = As[k][m];
                afr[mi][1] = As[k][m + 8];
                afr[mi][2] = As[k + 4][m];
                afr[mi][3] = As[k + 4][m + 8];
            }
            uint32_t bfr[8][2];
#pragma unroll
            for (int ni = 0; ni < 8; ni++) {
                int n = wn + ni * 8 + gid;
                bfr[ni][0] = Bs[k][n];
                bfr[ni][1] = Bs[k + 4][n];
            }
#pragma unroll
            for (int mi = 0; mi < 2; mi++)
#pragma unroll
                for (int ni = 0; ni < 8; ni++)
                    mma_tf32(acc[mi][ni], afr[mi], bfr[ni]);
        }
        __syncthreads();
    }

    // epilogue
#pragma unroll
    for (int mi = 0; mi < 2; mi++) {
        int m0 = row0 + wm + mi * 16 + gid;
#pragma unroll
        for (int ni = 0; ni < 8; ni++) {
            int n = col0 + wn + ni * 8 + tg * 2;
            if (n < N) {
                float bval0 = bias ? bias[n] : 0.f;
                float bval1 = bias ? bias[n + 1] : 0.f;
                float v0 = alpha * acc[mi][ni][0] + bval0;
                float v1 = alpha * acc[mi][ni][1] + bval1;
                float v2 = alpha * acc[mi][ni][2] + bval0;
                float v3 = alpha * acc[mi][ni][3] + bval1;
                if (relu) {
                    v0 = fmaxf(v0, 0.f); v1 = fmaxf(v1, 0.f);
                    v2 = fmaxf(v2, 0.f); v3 = fmaxf(v3, 0.f);
                }
                C[(long long)m0 * ldc + n]           = v0;
                C[(long long)m0 * ldc + n + 1]       = v1;
                C[(long long)(m0 + 8) * ldc + n]     = v2;
                C[(long long)(m0 + 8) * ldc + n + 1] = v3;
            }
        }
    }
}

// ---------------------------------------------------------------------------
// Softmax over rows of length T (one block per row)
// ---------------------------------------------------------------------------
__global__ __launch_bounds__(256) void softmax_kernel(float* __restrict__ Srows, int T)
{
    float* row = Srows + (long long)blockIdx.x * T;
    __shared__ float red[256];
    int tid = threadIdx.x;

    float m = -INFINITY;
    for (int i = tid; i < T; i += 256) m = fmaxf(m, row[i]);
    red[tid] = m; __syncthreads();
    for (int s = 128; s > 0; s >>= 1) {
        if (tid < s) red[tid] = fmaxf(red[tid], red[tid + s]);
        __syncthreads();
    }
    m = red[0]; __syncthreads();

    float sum = 0.f;
    for (int i = tid; i < T; i += 256) {
        float e = expf(row[i] - m);
        row[i] = e;
        sum += e;
    }
    red[tid] = sum; __syncthreads();
    for (int s = 128; s > 0; s >>= 1) {
        if (tid < s) red[tid] += red[tid + s];
        __syncthreads();
    }
    float inv = 1.f / red[0];
    for (int i = tid; i < T; i += 256) row[i] *= inv;
}

// ---------------------------------------------------------------------------
// LayerNorm with optional residual: O = LN(X + R) * g + b   (N = 2048)
// ---------------------------------------------------------------------------
__global__ __launch_bounds__(256) void ln_kernel(
    const float* __restrict__ X, const float* __restrict__ R,
    const float* __restrict__ g, const float* __restrict__ b,
    float* __restrict__ O)
{
    long long off = (long long)blockIdx.x * HD_;
    __shared__ float red[256];
    int tid = threadIdx.x;

    float xv[8];
    float lsum = 0.f;
#pragma unroll
    for (int i = 0; i < 8; i++) {
        int c = tid + i * 256;
        float x = X[off + c];
        if (R) x += R[off + c];
        xv[i] = x;
        lsum += x;
    }
    red[tid] = lsum; __syncthreads();
    for (int s = 128; s > 0; s >>= 1) {
        if (tid < s) red[tid] += red[tid + s];
        __syncthreads();
    }
    float mean = red[0] * (1.f / HD_);
    __syncthreads();

    float lvar = 0.f;
#pragma unroll
    for (int i = 0; i < 8; i++) {
        float d = xv[i] - mean;
        lvar += d * d;
    }
    red[tid] = lvar; __syncthreads();
    for (int s = 128; s > 0; s >>= 1) {
        if (tid < s) red[tid] += red[tid + s];
        __syncthreads();
    }
    float inv = rsqrtf(red[0] * (1.f / HD_) + 1e-5f);

#pragma unroll
    for (int i = 0; i < 8; i++) {
        int c = tid + i * 256;
        O[off + c] = (xv[i] - mean) * inv * g[c] + b[c];
    }
}

// ---------------------------------------------------------------------------
// Embedding gather: h[s,c] = tok[ids[s],c] + pos[s,c]
// ---------------------------------------------------------------------------
__global__ __launch_bounds__(256) void embed_kernel(
    const int* __restrict__ ids, const float* __restrict__ tok,
    const float* __restrict__ pos, float* __restrict__ h)
{
    long long idx = (long long)blockIdx.x * 256 + threadIdx.x;
    int c = (int)(idx & (HD_ - 1));
    int s = (int)(idx >> 11);
    h[idx] = tok[(long long)ids[s] * HD_ + c] + pos[idx];
}

// ---------------------------------------------------------------------------
// Weight pre-reductions (sum over sub-head axis j)
// ---------------------------------------------------------------------------
__global__ __launch_bounds__(256) void reduce_wq_kernel(
    const float* __restrict__ Wq, float* __restrict__ Wq_r)
{
    long long idx = (long long)blockIdx.x * 256 + threadIdx.x;
    int gd = (int)(idx & (GD_ - 1));
    int k  = (int)((idx >> 8) & (HD_ - 1));
    int l  = (int)(idx >> 19);
    int gg = gd >> 6, d = gd & 63;
    const float* row = Wq + (((long long)l * HD_ + k) * HD_) + gg * (GS_ * D_) + d;
    float s = 0.f;
#pragma unroll
    for (int j = 0; j < GS_; j++) s += row[j * D_];
    Wq_r[idx] = s;
}

__global__ __launch_bounds__(256) void reduce_bq_kernel(
    const float* __restrict__ bq, float* __restrict__ bq_r)
{
    int idx = blockIdx.x * 256 + threadIdx.x;
    if (idx >= L_ * GD_) return;
    int gd = idx & (GD_ - 1);
    int l  = idx >> 8;
    int gg = gd >> 6, d = gd & 63;
    const float* row = bq + (long long)l * HD_ + gg * (GS_ * D_) + d;
    float s = 0.f;
#pragma unroll
    for (int j = 0; j < GS_; j++) s += row[j * D_];
    bq_r[idx] = s;
}

__global__ __launch_bounds__(256) void reduce_wo_kernel(
    const float* __restrict__ Wo, float* __restrict__ Wo_r)
{
    long long idx = (long long)blockIdx.x * 256 + threadIdx.x;
    int n  = (int)(idx & (HD_ - 1));
    int gd = (int)((idx >> 11) & (GD_ - 1));
    int l  = (int)(idx >> 19);
    int gg = gd >> 6, d = gd & 63;
    float s = 0.f;
#pragma unroll
    for (int j = 0; j < GS_; j++)
        s += Wo[(((long long)l * HD_) + gg * (GS_ * D_) + j * D_ + d) * HD_ + n];
    Wo_r[idx] = s;
}

// K transpose: Kt[gd, t] = K[t, gd]
__global__ __launch_bounds__(256) void transpose_k_kernel(
    const float* __restrict__ Kk, float* __restrict__ Kt)
{
    long long idx = (long long)blockIdx.x * 256 + threadIdx.x;
    int t  = (int)(idx & (S_ - 1));
    int gd = (int)(idx >> 10);
    Kt[idx] = Kk[(long long)t * GD_ + gd];
}

// ---------------------------------------------------------------------------
// Host orchestration
// ---------------------------------------------------------------------------
static void launch_gemm(int M, int N, int K, float alpha,
                        const float* A, int lda, long long sA,
                        const float* B, int ldb, long long sB,
                        const float* bias,
                        float* C, int ldc, long long sC,
                        int batch, int relu)
{
    dim3 grid((N + BN - 1) / BN, (M + BM - 1) / BM, batch);
    tgemm_kernel<<<grid, 256>>>(M, N, K, alpha, A, lda, sA, B, ldb, sB,
                                bias, C, ldc, sC, relu);
}

extern "C" void kernel_launch(void* const* d_in, const int* in_sizes, int n_in,
                              void* d_out, int out_size)
{
    const int*   ids     = (const int*)  d_in[0];
    const float* tok_emb = (const float*)d_in[1];
    const float* pos_emb = (const float*)d_in[2];
    const float* Wq      = (const float*)d_in[3];
    const float* bq      = (const float*)d_in[4];
    const float* Wk      = (const float*)d_in[5];
    const float* bk      = (const float*)d_in[6];
    const float* Wv      = (const float*)d_in[7];
    const float* bv      = (const float*)d_in[8];
    const float* Wo      = (const float*)d_in[9];
    const float* bo      = (const float*)d_in[10];
    const float* g1      = (const float*)d_in[11];
    const float* be1     = (const float*)d_in[12];
    const float* W1      = (const float*)d_in[13];
    const float* b1      = (const float*)d_in[14];
    const float* W2      = (const float*)d_in[15];
    const float* b2      = (const float*)d_in[16];
    const float* g2      = (const float*)d_in[17];
    const float* be2     = (const float*)d_in[18];
    const float* lnf_g   = (const float*)d_in[19];
    const float* lnf_b   = (const float*)d_in[20];
    const float* Whead   = (const float*)d_in[21];
    float* out = (float*)d_out;

    float *Wq_r, *bq_r, *Wo_r, *h, *t2, *a1, *qr, *kk, *kt, *vv, *ctx, *sc;
    cudaGetSymbolAddress((void**)&Wq_r, g_Wq_r);
    cudaGetSymbolAddress((void**)&bq_r, g_bq_r);
    cudaGetSymbolAddress((void**)&Wo_r, g_Wo_r);
    cudaGetSymbolAddress((void**)&h,    g_h);
    cudaGetSymbolAddress((void**)&t2,   g_t2);
    cudaGetSymbolAddress((void**)&a1,   g_a1);
    cudaGetSymbolAddress((void**)&qr,   g_qr);
    cudaGetSymbolAddress((void**)&kk,   g_k);
    cudaGetSymbolAddress((void**)&kt,   g_kt);
    cudaGetSymbolAddress((void**)&vv,   g_v);
    cudaGetSymbolAddress((void**)&ctx,  g_ctx);
    cudaGetSymbolAddress((void**)&sc,   g_sc);

    // weight pre-reductions (sum over sub-head axis j)
    reduce_wq_kernel<<<(L_ * HD_ * GD_) / 256, 256>>>(Wq, Wq_r);
    reduce_bq_kernel<<<2, 256>>>(bq, bq_r);
    reduce_wo_kernel<<<(L_ * GD_ * HD_) / 256, 256>>>(Wo, Wo_r);

    // embedding
    embed_kernel<<<(S_ * HD_) / 256, 256>>>(ids, tok_emb, pos_emb, h);

    for (int l = 0; l < L_; l++) {
        const float* Wq_l = Wq_r + (long long)l * HD_ * GD_;
        const float* bq_l = bq_r + (long long)l * GD_;
        const float* Wk_l = Wk   + (long long)l * HD_ * GD_;
        const float* bk_l = bk   + (long long)l * GD_;
        const float* Wv_l = Wv   + (long long)l * HD_ * GD_;
        const float* bv_l = bv   + (long long)l * GD_;
        const float* Wo_l = Wo_r + (long long)l * GD_ * HD_;
        const float* bo_l = bo   + (long long)l * HD_;
        const float* W1_l = W1   + (long long)l * HD_ * FF_;
        const float* b1_l = b1   + (long long)l * FF_;
        const float* W2_l = W2   + (long long)l * FF_ * HD_;
        const float* b2_l = b2   + (long long)l * HD_;

        // Q-sum / K / V projections  [S,HD] @ [HD,GD]
        launch_gemm(S_, GD_, HD_, 1.f, h, HD_, 0, Wq_l, GD_, 0, bq_l, qr, GD_, 0, 1, 0);
        launch_gemm(S_, GD_, HD_, 1.f, h, HD_, 0, Wk_l, GD_, 0, bk_l, kk, GD_, 0, 1, 0);
        launch_gemm(S_, GD_, HD_, 1.f, h, HD_, 0, Wv_l, GD_, 0, bv_l, vv, GD_, 0, 1, 0);

        // K transpose
        transpose_k_kernel<<<(GD_ * S_) / 256, 256>>>(kk, kt);

        // scores[g] = (1/8) * Qsum_g @ K_g^T
        launch_gemm(S_, S_, D_, 0.125f,
                    qr, GD_, D_,
                    kt, S_, (long long)D_ * S_,
                    nullptr,
                    sc, S_, (long long)S_ * S_,
                    G_, 0);

        softmax_kernel<<<G_ * S_, 256>>>(sc, S_);

        // ctx[g] = attn_g @ V_g
        launch_gemm(S_, D_, S_, 1.f,
                    sc, S_, (long long)S_ * S_,
                    vv, GD_, D_,
                    nullptr,
                    ctx, GD_, D_,
                    G_, 0);

        // attn_out = ctx @ Wo_r + bo ; h = LN(h + attn_out)
        launch_gemm(S_, HD_, GD_, 1.f, ctx, GD_, 0, Wo_l, HD_, 0, bo_l, t2, HD_, 0, 1, 0);
        ln_kernel<<<S_, 256>>>(h, t2, g1 + (long long)l * HD_, be1 + (long long)l * HD_, h);

        // FFN
        launch_gemm(S_, FF_, HD_, 1.f, h, HD_, 0, W1_l, FF_, 0, b1_l, a1, FF_, 0, 1, 1);
        launch_gemm(S_, HD_, FF_, 1.f, a1, FF_, 0, W2_l, HD_, 0, b2_l, t2, HD_, 0, 1, 0);
        ln_kernel<<<S_, 256>>>(h, t2, g2 + (long long)l * HD_, be2 + (long long)l * HD_, h);
    }

    // final LN + lm head
    ln_kernel<<<S_, 256>>>(h, nullptr, lnf_g, lnf_b, t2);
    launch_gemm(S_, V_, HD_, 1.f, t2, HD_, 0, Whead, V_, 0, nullptr, out, V_, 0, 1, 0);
}

// round 5
// speedup vs baseline: 4.5547x; 1.8738x over previous
#include <cuda_runtime.h>
#include <cuda_bf16.h>
#include <math.h>
#include <stdint.h>

// ---------------------------------------------------------------------------
// Problem constants
// ---------------------------------------------------------------------------
#define S_   1024
#define HD_  2048
#define L_   2
#define G_   4
#define D_   64
#define GS_  8
#define GD_  (G_ * D_)       // 256
#define QKV_ 768             // packed q(256)+k(256)+v(256)
#define FF_  8192
#define V_   38400

// ---------------------------------------------------------------------------
// Scratch (device globals -- no allocation allowed)
// ---------------------------------------------------------------------------
__device__ float g_Wqkv[L_ * HD_ * QKV_];   // packed [Wq_r | Wk | Wv]
__device__ float g_bqkv[L_ * QKV_];
__device__ float g_Wo_r[L_ * GD_ * HD_];
__device__ float g_h   [S_ * HD_];
__device__ float g_t2  [S_ * HD_];
__device__ float g_a1  [S_ * FF_];
__device__ float g_qkv [S_ * QKV_];
__device__ float g_kt  [GD_ * S_];
__device__ float g_ctx [S_ * GD_];
__device__ float g_sc  [G_ * S_ * S_];

// ---------------------------------------------------------------------------
// helpers
// ---------------------------------------------------------------------------
__device__ __forceinline__ uint32_t f2tf32(float f) {
    uint32_t r;
    asm("cvt.rna.tf32.f32 %0, %1;" : "=r"(r) : "f"(f));
    return r;
}

__device__ __forceinline__ void mma_tf32(float c[4], const uint32_t a[4], const uint32_t b[2]) {
    asm volatile(
        "mma.sync.aligned.m16n8k8.row.col.f32.tf32.tf32.f32 "
        "{%0,%1,%2,%3}, {%4,%5,%6,%7}, {%8,%9}, {%0,%1,%2,%3};"
        : "+f"(c[0]), "+f"(c[1]), "+f"(c[2]), "+f"(c[3])
        : "r"(a[0]), "r"(a[1]), "r"(a[2]), "r"(a[3]),
          "r"(b[0]), "r"(b[1]));
}

__device__ __forceinline__ void cp16(uint32_t smem_b, const float* g) {
    asm volatile("cp.async.cg.shared.global [%0], [%1], 16;\n"
                 :: "r"(smem_b), "l"(g));
}

// ---------------------------------------------------------------------------
// tf32 tensor-core GEMM, cp.async double-buffered.
// BM=128 fixed, 4 warps (2x2) of 64xWN_, BKT=32.
// A smem layout [m][k] pitch 36 words; B smem [k][n] pitch BN_+8.
// Requires: M%128==0, N%BN_==0, K%32==0, 16B-aligned rows.
// ---------------------------------------------------------------------------
#define BKT 32
#define AP  36

template<int BN_, int WN_>
__global__ __launch_bounds__(128, 2) void tgemm_kernel(
    int M, int N, int K, float alpha,
    const float* __restrict__ A, int lda, long long sA,
    const float* __restrict__ B, int ldb, long long sB,
    const float* __restrict__ bias,
    float* __restrict__ C, int ldc, long long sC,
    int relu)
{
    constexpr int BPW = BN_ + 8;
    constexpr int NI  = WN_ / 8;
    constexpr int NBV = BN_ / 16;            // B float4 vectors per thread
    constexpr int AS_WORDS = 2 * 128 * AP;   // double-buffered A
    extern __shared__ float smf[];
    float* Asm = smf;                         // [2][128][AP]
    float* Bsm = smf + AS_WORDS;              // [2][32][BPW]

    long long bz = blockIdx.z;
    A += bz * sA;
    B += bz * sB;
    C += bz * sC;

    const int row0 = blockIdx.y * 128;
    const int col0 = blockIdx.x * BN_;
    const int tid  = threadIdx.x;
    const int lane = tid & 31;
    const int warp = tid >> 5;
    const int wm   = (warp & 1) * 64;
    const int wn   = (warp >> 1) * WN_;
    const int gid  = lane >> 2;
    const int tg   = lane & 3;

    uint32_t As_b = (uint32_t)__cvta_generic_to_shared(Asm);
    uint32_t Bs_b = (uint32_t)__cvta_generic_to_shared(Bsm);

    const int T = K / BKT;

    // ---- async tile issue ----
    auto issue_tile = [&](int kt, int buf) {
        const float* Ag = A + (long long)row0 * lda + kt * BKT;
#pragma unroll
        for (int p = 0; p < 8; p++) {
            int v   = p * 128 + tid;
            int row = v >> 3;
            int ch  = (v & 7) * 4;
            cp16(As_b + (uint32_t)(((buf * 128 + row) * AP + ch) * 4),
                 Ag + (long long)row * lda + ch);
        }
        const float* Bg = B + (long long)(kt * BKT) * ldb + col0;
#pragma unroll
        for (int p = 0; p < NBV; p++) {
            int v  = p * 128 + tid;
            int kr = v / (BN_ / 4);
            int ch = (v % (BN_ / 4)) * 4;
            cp16(Bs_b + (uint32_t)(((buf * 32 + kr) * BPW + ch) * 4),
                 Bg + (long long)kr * ldb + ch);
        }
        asm volatile("cp.async.commit_group;\n" ::);
    };

    float acc[4][NI][4];
#pragma unroll
    for (int mi = 0; mi < 4; mi++)
#pragma unroll
        for (int ni = 0; ni < NI; ni++)
#pragma unroll
            for (int c = 0; c < 4; c++) acc[mi][ni][c] = 0.f;

    // prologue: 2 tiles in flight
    issue_tile(0, 0);
    issue_tile(1, 1);
    asm volatile("cp.async.wait_group 1;\n" ::);
    __syncthreads();

    for (int i = 0; i < T; i++) {
        const int buf = i & 1;
        const float* Ab = Asm + buf * 128 * AP;
        const float* Bb = Bsm + buf * 32 * BPW;

#pragma unroll
        for (int ks = 0; ks < 4; ks++) {
            const int k = ks * 8 + tg;
            uint32_t afr[4][4];
#pragma unroll
            for (int mi = 0; mi < 4; mi++) {
                int m = wm + mi * 16 + gid;
                afr[mi][0] = f2tf32(Ab[m * AP + k]);
                afr[mi][1] = f2tf32(Ab[(m + 8) * AP + k]);
                afr[mi][2] = f2tf32(Ab[m * AP + k + 4]);
                afr[mi][3] = f2tf32(Ab[(m + 8) * AP + k + 4]);
            }
            uint32_t bfr[NI][2];
#pragma unroll
            for (int ni = 0; ni < NI; ni++) {
                int n = wn + ni * 8 + gid;
                bfr[ni][0] = f2tf32(Bb[k * BPW + n]);
                bfr[ni][1] = f2tf32(Bb[(k + 4) * BPW + n]);
            }
#pragma unroll
            for (int mi = 0; mi < 4; mi++)
#pragma unroll
                for (int ni = 0; ni < NI; ni++)
                    mma_tf32(acc[mi][ni], afr[mi], bfr[ni]);
        }

        if (i + 1 < T) {
            __syncthreads();                    // all warps done with buf
            if (i + 2 < T) {
                issue_tile(i + 2, buf);
                asm volatile("cp.async.wait_group 1;\n" ::);
            } else {
                asm volatile("cp.async.wait_group 0;\n" ::);
            }
            __syncthreads();                    // tile i+1 visible everywhere
        }
    }

    // epilogue
#pragma unroll
    for (int mi = 0; mi < 4; mi++) {
        int m0 = row0 + wm + mi * 16 + gid;
#pragma unroll
        for (int ni = 0; ni < NI; ni++) {
            int n = col0 + wn + ni * 8 + tg * 2;
            float b0 = bias ? bias[n]     : 0.f;
            float b1 = bias ? bias[n + 1] : 0.f;
            float v0 = alpha * acc[mi][ni][0] + b0;
            float v1 = alpha * acc[mi][ni][1] + b1;
            float v2 = alpha * acc[mi][ni][2] + b0;
            float v3 = alpha * acc[mi][ni][3] + b1;
            if (relu) {
                v0 = fmaxf(v0, 0.f); v1 = fmaxf(v1, 0.f);
                v2 = fmaxf(v2, 0.f); v3 = fmaxf(v3, 0.f);
            }
            *(float2*)(C + (long long)m0 * ldc + n)       = make_float2(v0, v1);
            *(float2*)(C + (long long)(m0 + 8) * ldc + n) = make_float2(v2, v3);
        }
    }
}

// ---------------------------------------------------------------------------
// Softmax over rows of length T (one block per row)
// ---------------------------------------------------------------------------
__global__ __launch_bounds__(256) void softmax_kernel(float* __restrict__ Srows, int T)
{
    float* row = Srows + (long long)blockIdx.x * T;
    __shared__ float red[256];
    int tid = threadIdx.x;

    float m = -INFINITY;
    for (int i = tid; i < T; i += 256) m = fmaxf(m, row[i]);
    red[tid] = m; __syncthreads();
    for (int s = 128; s > 0; s >>= 1) {
        if (tid < s) red[tid] = fmaxf(red[tid], red[tid + s]);
        __syncthreads();
    }
    m = red[0]; __syncthreads();

    float sum = 0.f;
    for (int i = tid; i < T; i += 256) {
        float e = expf(row[i] - m);
        row[i] = e;
        sum += e;
    }
    red[tid] = sum; __syncthreads();
    for (int s = 128; s > 0; s >>= 1) {
        if (tid < s) red[tid] += red[tid + s];
        __syncthreads();
    }
    float inv = 1.f / red[0];
    for (int i = tid; i < T; i += 256) row[i] *= inv;
}

// ---------------------------------------------------------------------------
// LayerNorm with optional residual: O = LN(X + R) * g + b   (N = 2048)
// ---------------------------------------------------------------------------
__global__ __launch_bounds__(256) void ln_kernel(
    const float* __restrict__ X, const float* __restrict__ R,
    const float* __restrict__ g, const float* __restrict__ b,
    float* __restrict__ O)
{
    long long off = (long long)blockIdx.x * HD_;
    __shared__ float red[256];
    int tid = threadIdx.x;

    float xv[8];
    float lsum = 0.f;
#pragma unroll
    for (int i = 0; i < 8; i++) {
        int c = tid + i * 256;
        float x = X[off + c];
        if (R) x += R[off + c];
        xv[i] = x;
        lsum += x;
    }
    red[tid] = lsum; __syncthreads();
    for (int s = 128; s > 0; s >>= 1) {
        if (tid < s) red[tid] += red[tid + s];
        __syncthreads();
    }
    float mean = red[0] * (1.f / HD_);
    __syncthreads();

    float lvar = 0.f;
#pragma unroll
    for (int i = 0; i < 8; i++) {
        float d = xv[i] - mean;
        lvar += d * d;
    }
    red[tid] = lvar; __syncthreads();
    for (int s = 128; s > 0; s >>= 1) {
        if (tid < s) red[tid] += red[tid + s];
        __syncthreads();
    }
    float inv = rsqrtf(red[0] * (1.f / HD_) + 1e-5f);

#pragma unroll
    for (int i = 0; i < 8; i++) {
        int c = tid + i * 256;
        O[off + c] = (xv[i] - mean) * inv * g[c] + b[c];
    }
}

// ---------------------------------------------------------------------------
// Embedding gather: h[s,c] = tok[ids[s],c] + pos[s,c]
// ---------------------------------------------------------------------------
__global__ __launch_bounds__(256) void embed_kernel(
    const int* __restrict__ ids, const float* __restrict__ tok,
    const float* __restrict__ pos, float* __restrict__ h)
{
    long long idx = (long long)blockIdx.x * 256 + threadIdx.x;
    int c = (int)(idx & (HD_ - 1));
    int s = (int)(idx >> 11);
    h[idx] = tok[(long long)ids[s] * HD_ + c] + pos[idx];
}

// ---------------------------------------------------------------------------
// Build packed QKV weights: Wqkv[l][k][0:256]=sum_j Wq, [256:512]=Wk, [512:768]=Wv
// ---------------------------------------------------------------------------
__global__ __launch_bounds__(256) void pack_wqkv_kernel(
    const float* __restrict__ Wq, const float* __restrict__ Wk,
    const float* __restrict__ Wv, float* __restrict__ Wqkv)
{
    long long idx = (long long)blockIdx.x * 256 + threadIdx.x;  // L*HD*768
    if (idx >= (long long)L_ * HD_ * QKV_) return;
    int col = (int)(idx % QKV_);
    long long rk = idx / QKV_;           // l*HD + k
    int k = (int)(rk & (HD_ - 1));
    int l = (int)(rk >> 11);
    float v;
    if (col < 256) {
        int gg = col >> 6, d = col & 63;
        const float* row = Wq + (((long long)l * HD_ + k) * HD_) + gg * (GS_ * D_) + d;
        float s = 0.f;
#pragma unroll
        for (int j = 0; j < GS_; j++) s += row[j * D_];
        v = s;
    } else if (col < 512) {
        v = Wk[((long long)l * HD_ + k) * GD_ + (col - 256)];
    } else {
        v = Wv[((long long)l * HD_ + k) * GD_ + (col - 512)];
    }
    Wqkv[idx] = v;
}

__global__ __launch_bounds__(256) void pack_bqkv_kernel(
    const float* __restrict__ bq, const float* __restrict__ bk,
    const float* __restrict__ bv, float* __restrict__ bqkv)
{
    int idx = blockIdx.x * 256 + threadIdx.x;   // L*768
    if (idx >= L_ * QKV_) return;
    int col = idx % QKV_;
    int l   = idx / QKV_;
    float v;
    if (col < 256) {
        int gg = col >> 6, d = col & 63;
        const float* row = bq + (long long)l * HD_ + gg * (GS_ * D_) + d;
        float s = 0.f;
#pragma unroll
        for (int j = 0; j < GS_; j++) s += row[j * D_];
        v = s;
    } else if (col < 512) {
        v = bk[(long long)l * GD_ + (col - 256)];
    } else {
        v = bv[(long long)l * GD_ + (col - 512)];
    }
    bqkv[idx] = v;
}

__global__ __launch_bounds__(256) void reduce_wo_kernel(
    const float* __restrict__ Wo, float* __restrict__ Wo_r)
{
    long long idx = (long long)blockIdx.x * 256 + threadIdx.x;
    int n  = (int)(idx & (HD_ - 1));
    int gd = (int)((idx >> 11) & (GD_ - 1));
    int l  = (int)(idx >> 19);
    int gg = gd >> 6, d = gd & 63;
    float s = 0.f;
#pragma unroll
    for (int j = 0; j < GS_; j++)
        s += Wo[(((long long)l * HD_) + gg * (GS_ * D_) + j * D_ + d) * HD_ + n];
    Wo_r[idx] = s;
}

// K transpose out of packed qkv: kt[gd][t] = qkv[t][256+gd]
__global__ __launch_bounds__(256) void transpose_k_kernel(
    const float* __restrict__ qkv, float* __restrict__ Kt)
{
    long long idx = (long long)blockIdx.x * 256 + threadIdx.x;  // GD*S
    int t  = (int)(idx & (S_ - 1));
    int gd = (int)(idx >> 10);
    Kt[idx] = qkv[(long long)t * QKV_ + 256 + gd];
}

// ---------------------------------------------------------------------------
// Host orchestration
// ---------------------------------------------------------------------------
static const int SMEM_BN128 = (2 * 128 * AP + 2 * 32 * (128 + 8)) * 4;  // 71680
static const int SMEM_BN64  = (2 * 128 * AP + 2 * 32 * (64 + 8)) * 4;   // 55296

static void launch_gemm128(int M, int N, int K, float alpha,
                           const float* A, int lda, long long sA,
                           const float* B, int ldb, long long sB,
                           const float* bias,
                           float* C, int ldc, long long sC,
                           int batch, int relu)
{
    dim3 grid(N / 128, M / 128, batch);
    tgemm_kernel<128, 64><<<grid, 128, SMEM_BN128>>>(
        M, N, K, alpha, A, lda, sA, B, ldb, sB, bias, C, ldc, sC, relu);
}

static void launch_gemm64(int M, int N, int K, float alpha,
                          const float* A, int lda, long long sA,
                          const float* B, int ldb, long long sB,
                          const float* bias,
                          float* C, int ldc, long long sC,
                          int batch, int relu)
{
    dim3 grid(N / 64, M / 128, batch);
    tgemm_kernel<64, 32><<<grid, 128, SMEM_BN64>>>(
        M, N, K, alpha, A, lda, sA, B, ldb, sB, bias, C, ldc, sC, relu);
}

extern "C" void kernel_launch(void* const* d_in, const int* in_sizes, int n_in,
                              void* d_out, int out_size)
{
    const int*   ids     = (const int*)  d_in[0];
    const float* tok_emb = (const float*)d_in[1];
    const float* pos_emb = (const float*)d_in[2];
    const float* Wq      = (const float*)d_in[3];
    const float* bq      = (const float*)d_in[4];
    const float* Wk      = (const float*)d_in[5];
    const float* bk      = (const float*)d_in[6];
    const float* Wv      = (const float*)d_in[7];
    const float* bv      = (const float*)d_in[8];
    const float* Wo      = (const float*)d_in[9];
    const float* bo      = (const float*)d_in[10];
    const float* g1      = (const float*)d_in[11];
    const float* be1     = (const float*)d_in[12];
    const float* W1      = (const float*)d_in[13];
    const float* b1      = (const float*)d_in[14];
    const float* W2      = (const float*)d_in[15];
    const float* b2      = (const float*)d_in[16];
    const float* g2      = (const float*)d_in[17];
    const float* be2     = (const float*)d_in[18];
    const float* lnf_g   = (const float*)d_in[19];
    const float* lnf_b   = (const float*)d_in[20];
    const float* Whead   = (const float*)d_in[21];
    float* out = (float*)d_out;

    static int smem_set = 0;
    if (!smem_set) {
        cudaFuncSetAttribute(tgemm_kernel<128, 64>,
                             cudaFuncAttributeMaxDynamicSharedMemorySize, SMEM_BN128);
        cudaFuncSetAttribute(tgemm_kernel<64, 32>,
                             cudaFuncAttributeMaxDynamicSharedMemorySize, SMEM_BN64);
        smem_set = 1;
    }

    float *Wqkv, *bqkv, *Wo_r, *h, *t2, *a1, *qkv, *kt, *ctx, *sc;
    cudaGetSymbolAddress((void**)&Wqkv, g_Wqkv);
    cudaGetSymbolAddress((void**)&bqkv, g_bqkv);
    cudaGetSymbolAddress((void**)&Wo_r, g_Wo_r);
    cudaGetSymbolAddress((void**)&h,    g_h);
    cudaGetSymbolAddress((void**)&t2,   g_t2);
    cudaGetSymbolAddress((void**)&a1,   g_a1);
    cudaGetSymbolAddress((void**)&qkv,  g_qkv);
    cudaGetSymbolAddress((void**)&kt,   g_kt);
    cudaGetSymbolAddress((void**)&ctx,  g_ctx);
    cudaGetSymbolAddress((void**)&sc,   g_sc);

    // weight packing / pre-reductions
    long long nwq = (long long)L_ * HD_ * QKV_;
    pack_wqkv_kernel<<<(int)((nwq + 255) / 256), 256>>>(Wq, Wk, Wv, Wqkv);
    pack_bqkv_kernel<<<(L_ * QKV_ + 255) / 256, 256>>>(bq, bk, bv, bqkv);
    reduce_wo_kernel<<<(L_ * GD_ * HD_) / 256, 256>>>(Wo, Wo_r);

    // embedding
    embed_kernel<<<(S_ * HD_) / 256, 256>>>(ids, tok_emb, pos_emb, h);

    for (int l = 0; l < L_; l++) {
        const float* Wqkv_l = Wqkv + (long long)l * HD_ * QKV_;
        const float* bqkv_l = bqkv + (long long)l * QKV_;
        const float* Wo_l   = Wo_r + (long long)l * GD_ * HD_;
        const float* bo_l   = bo   + (long long)l * HD_;
        const float* W1_l   = W1   + (long long)l * HD_ * FF_;
        const float* b1_l   = b1   + (long long)l * FF_;
        const float* W2_l   = W2   + (long long)l * FF_ * HD_;
        const float* b2_l   = b2   + (long long)l * HD_;

        // fused QKV projection  [S,HD] @ [HD,768]
        launch_gemm128(S_, QKV_, HD_, 1.f, h, HD_, 0, Wqkv_l, QKV_, 0,
                       bqkv_l, qkv, QKV_, 0, 1, 0);

        // K transpose
        transpose_k_kernel<<<(GD_ * S_) / 256, 256>>>(qkv, kt);

        // scores[g] = (1/8) * Qsum_g @ K_g^T
        launch_gemm128(S_, S_, D_, 0.125f,
                       qkv, QKV_, 64,
                       kt, S_, (long long)D_ * S_,
                       nullptr,
                       sc, S_, (long long)S_ * S_,
                       G_, 0);

        softmax_kernel<<<G_ * S_, 256>>>(sc, S_);

        // ctx[g] = attn_g @ V_g
        launch_gemm64(S_, D_, S_, 1.f,
                      sc, S_, (long long)S_ * S_,
                      qkv + 512, QKV_, 64,
                      nullptr,
                      ctx, GD_, D_,
                      G_, 0);

        // attn_out = ctx @ Wo_r + bo ; h = LN(h + attn_out)
        launch_gemm128(S_, HD_, GD_, 1.f, ctx, GD_, 0, Wo_l, HD_, 0,
                       bo_l, t2, HD_, 0, 1, 0);
        ln_kernel<<<S_, 256>>>(h, t2, g1 + (long long)l * HD_, be1 + (long long)l * HD_, h);

        // FFN
        launch_gemm128(S_, FF_, HD_, 1.f, h, HD_, 0, W1_l, FF_, 0,
                       b1_l, a1, FF_, 0, 1, 1);
        launch_gemm128(S_, HD_, FF_, 1.f, a1, FF_, 0, W2_l, HD_, 0,
                       b2_l, t2, HD_, 0, 1, 0);
        ln_kernel<<<S_, 256>>>(h, t2, g2 + (long long)l * HD_, be2 + (long long)l * HD_, h);
    }

    // final LN + lm head
    ln_kernel<<<S_, 256>>>(h, nullptr, lnf_g, lnf_b, t2);
    launch_gemm128(S_, V_, HD_, 1.f, t2, HD_, 0, Whead, V_, 0, nullptr, out, V_, 0, 1, 0);
}

// round 6
// speedup vs baseline: 4.5654x; 1.0023x over previous
#include <cuda_runtime.h>
#include <cuda_bf16.h>
#include <math.h>
#include <stdint.h>

// ---------------------------------------------------------------------------
// Problem constants
// ---------------------------------------------------------------------------
#define S_   1024
#define HD_  2048
#define L_   2
#define G_   4
#define D_   64
#define GS_  8
#define GD_  (G_ * D_)       // 256
#define QKV_ 768             // packed q(256)+k(256)+v(256)
#define FF_  8192
#define V_   38400

// ---------------------------------------------------------------------------
// Scratch (device globals -- no allocation allowed)
// ---------------------------------------------------------------------------
__device__ float g_Wqkv[L_ * HD_ * QKV_];   // packed [Wq_r | Wk | Wv]
__device__ float g_bqkv[L_ * QKV_];
__device__ float g_Wo_r[L_ * GD_ * HD_];
__device__ float g_h   [S_ * HD_];
__device__ float g_t2  [S_ * HD_];
__device__ float g_a1  [S_ * FF_];
__device__ float g_qkv [S_ * QKV_];
__device__ float g_kt  [GD_ * S_];
__device__ float g_ctx [S_ * GD_];
__device__ float g_sc  [G_ * S_ * S_];

// ---------------------------------------------------------------------------
// helpers
// ---------------------------------------------------------------------------
__device__ __forceinline__ uint32_t f2tf32(float f) {
    uint32_t r;
    asm("cvt.rna.tf32.f32 %0, %1;" : "=r"(r) : "f"(f));
    return r;
}

__device__ __forceinline__ void mma_tf32(float c[4], const uint32_t a[4], const uint32_t b[2]) {
    asm volatile(
        "mma.sync.aligned.m16n8k8.row.col.f32.tf32.tf32.f32 "
        "{%0,%1,%2,%3}, {%4,%5,%6,%7}, {%8,%9}, {%0,%1,%2,%3};"
        : "+f"(c[0]), "+f"(c[1]), "+f"(c[2]), "+f"(c[3])
        : "r"(a[0]), "r"(a[1]), "r"(a[2]), "r"(a[3]),
          "r"(b[0]), "r"(b[1]));
}

__device__ __forceinline__ void cp16(uint32_t smem_b, const float* g) {
    asm volatile("cp.async.cg.shared.global [%0], [%1], 16;\n"
                 :: "r"(smem_b), "l"(g));
}

// ---------------------------------------------------------------------------
// tf32 tensor-core GEMM, cp.async double-buffered.
// BM=128 fixed, 4 warps (2x2) of 64xWN_, BKT=32.
// A smem layout [m][k] pitch 36 words; B smem [k][n] pitch BN_+8.
// Requires: M%128==0, N%BN_==0, K%32==0, 16B-aligned rows.
// ---------------------------------------------------------------------------
#define BKT 32
#define AP  36

template<int BN_, int WN_>
__global__ __launch_bounds__(128, 2) void tgemm_kernel(
    int M, int N, int K, float alpha,
    const float* __restrict__ A, int lda, long long sA,
    const float* __restrict__ B, int ldb, long long sB,
    const float* __restrict__ bias,
    float* __restrict__ C, int ldc, long long sC,
    int relu)
{
    constexpr int BPW = BN_ + 8;
    constexpr int NI  = WN_ / 8;
    constexpr int NBV = BN_ / 16;            // B float4 vectors per thread
    constexpr int AS_WORDS = 2 * 128 * AP;   // double-buffered A
    extern __shared__ float smf[];
    float* Asm = smf;                         // [2][128][AP]
    float* Bsm = smf + AS_WORDS;              // [2][32][BPW]

    long long bz = blockIdx.z;
    A += bz * sA;
    B += bz * sB;
    C += bz * sC;

    const int row0 = blockIdx.y * 128;
    const int col0 = blockIdx.x * BN_;
    const int tid  = threadIdx.x;
    const int lane = tid & 31;
    const int warp = tid >> 5;
    const int wm   = (warp & 1) * 64;
    const int wn   = (warp >> 1) * WN_;
    const int gid  = lane >> 2;
    const int tg   = lane & 3;

    uint32_t As_b = (uint32_t)__cvta_generic_to_shared(Asm);
    uint32_t Bs_b = (uint32_t)__cvta_generic_to_shared(Bsm);

    const int T = K / BKT;

    // ---- async tile issue ----
    auto issue_tile = [&](int kt, int buf) {
        const float* Ag = A + (long long)row0 * lda + kt * BKT;
#pragma unroll
        for (int p = 0; p < 8; p++) {
            int v   = p * 128 + tid;
            int row = v >> 3;
            int ch  = (v & 7) * 4;
            cp16(As_b + (uint32_t)(((buf * 128 + row) * AP + ch) * 4),
                 Ag + (long long)row * lda + ch);
        }
        const float* Bg = B + (long long)(kt * BKT) * ldb + col0;
#pragma unroll
        for (int p = 0; p < NBV; p++) {
            int v  = p * 128 + tid;
            int kr = v / (BN_ / 4);
            int ch = (v % (BN_ / 4)) * 4;
            cp16(Bs_b + (uint32_t)(((buf * 32 + kr) * BPW + ch) * 4),
                 Bg + (long long)kr * ldb + ch);
        }
        asm volatile("cp.async.commit_group;\n" ::);
    };

    float acc[4][NI][4];
#pragma unroll
    for (int mi = 0; mi < 4; mi++)
#pragma unroll
        for (int ni = 0; ni < NI; ni++)
#pragma unroll
            for (int c = 0; c < 4; c++) acc[mi][ni][c] = 0.f;

    // prologue: 2 tiles in flight
    issue_tile(0, 0);
    issue_tile(1, 1);
    asm volatile("cp.async.wait_group 1;\n" ::);
    __syncthreads();

    for (int i = 0; i < T; i++) {
        const int buf = i & 1;
        const float* Ab = Asm + buf * 128 * AP;
        const float* Bb = Bsm + buf * 32 * BPW;

#pragma unroll
        for (int ks = 0; ks < 4; ks++) {
            const int k = ks * 8 + tg;
            uint32_t afr[4][4];
#pragma unroll
            for (int mi = 0; mi < 4; mi++) {
                int m = wm + mi * 16 + gid;
                afr[mi][0] = f2tf32(Ab[m * AP + k]);
                afr[mi][1] = f2tf32(Ab[(m + 8) * AP + k]);
                afr[mi][2] = f2tf32(Ab[m * AP + k + 4]);
                afr[mi][3] = f2tf32(Ab[(m + 8) * AP + k + 4]);
            }
            uint32_t bfr[NI][2];
#pragma unroll
            for (int ni = 0; ni < NI; ni++) {
                int n = wn + ni * 8 + gid;
                bfr[ni][0] = f2tf32(Bb[k * BPW + n]);
                bfr[ni][1] = f2tf32(Bb[(k + 4) * BPW + n]);
            }
#pragma unroll
            for (int mi = 0; mi < 4; mi++)
#pragma unroll
                for (int ni = 0; ni < NI; ni++)
                    mma_tf32(acc[mi][ni], afr[mi], bfr[ni]);
        }

        if (i + 1 < T) {
            __syncthreads();                    // all warps done with buf
            if (i + 2 < T) {
                issue_tile(i + 2, buf);
                asm volatile("cp.async.wait_group 1;\n" ::);
            } else {
                asm volatile("cp.async.wait_group 0;\n" ::);
            }
            __syncthreads();                    // tile i+1 visible everywhere
        }
    }

    // epilogue
#pragma unroll
    for (int mi = 0; mi < 4; mi++) {
        int m0 = row0 + wm + mi * 16 + gid;
#pragma unroll
        for (int ni = 0; ni < NI; ni++) {
            int n = col0 + wn + ni * 8 + tg * 2;
            float b0 = bias ? bias[n]     : 0.f;
            float b1 = bias ? bias[n + 1] : 0.f;
            float v0 = alpha * acc[mi][ni][0] + b0;
            float v1 = alpha * acc[mi][ni][1] + b1;
            float v2 = alpha * acc[mi][ni][2] + b0;
            float v3 = alpha * acc[mi][ni][3] + b1;
            if (relu) {
                v0 = fmaxf(v0, 0.f); v1 = fmaxf(v1, 0.f);
                v2 = fmaxf(v2, 0.f); v3 = fmaxf(v3, 0.f);
            }
            *(float2*)(C + (long long)m0 * ldc + n)       = make_float2(v0, v1);
            *(float2*)(C + (long long)(m0 + 8) * ldc + n) = make_float2(v2, v3);
        }
    }
}

// ---------------------------------------------------------------------------
// Softmax over rows of length T (one block per row)
// ---------------------------------------------------------------------------
__global__ __launch_bounds__(256) void softmax_kernel(float* __restrict__ Srows, int T)
{
    float* row = Srows + (long long)blockIdx.x * T;
    __shared__ float red[256];
    int tid = threadIdx.x;

    float m = -INFINITY;
    for (int i = tid; i < T; i += 256) m = fmaxf(m, row[i]);
    red[tid] = m; __syncthreads();
    for (int s = 128; s > 0; s >>= 1) {
        if (tid < s) red[tid] = fmaxf(red[tid], red[tid + s]);
        __syncthreads();
    }
    m = red[0]; __syncthreads();

    float sum = 0.f;
    for (int i = tid; i < T; i += 256) {
        float e = expf(row[i] - m);
        row[i] = e;
        sum += e;
    }
    red[tid] = sum; __syncthreads();
    for (int s = 128; s > 0; s >>= 1) {
        if (tid < s) red[tid] += red[tid + s];
        __syncthreads();
    }
    float inv = 1.f / red[0];
    for (int i = tid; i < T; i += 256) row[i] *= inv;
}

// ---------------------------------------------------------------------------
// LayerNorm with optional residual: O = LN(X + R) * g + b   (N = 2048)
// ---------------------------------------------------------------------------
__global__ __launch_bounds__(256) void ln_kernel(
    const float* __restrict__ X, const float* __restrict__ R,
    const float* __restrict__ g, const float* __restrict__ b,
    float* __restrict__ O)
{
    long long off = (long long)blockIdx.x * HD_;
    __shared__ float red[256];
    int tid = threadIdx.x;

    float xv[8];
    float lsum = 0.f;
#pragma unroll
    for (int i = 0; i < 8; i++) {
        int c = tid + i * 256;
        float x = X[off + c];
        if (R) x += R[off + c];
        xv[i] = x;
        lsum += x;
    }
    red[tid] = lsum; __syncthreads();
    for (int s = 128; s > 0; s >>= 1) {
        if (tid < s) red[tid] += red[tid + s];
        __syncthreads();
    }
    float mean = red[0] * (1.f / HD_);
    __syncthreads();

    float lvar = 0.f;
#pragma unroll
    for (int i = 0; i < 8; i++) {
        float d = xv[i] - mean;
        lvar += d * d;
    }
    red[tid] = lvar; __syncthreads();
    for (int s = 128; s > 0; s >>= 1) {
        if (tid < s) red[tid] += red[tid + s];
        __syncthreads();
    }
    float inv = rsqrtf(red[0] * (1.f / HD_) + 1e-5f);

#pragma unroll
    for (int i = 0; i < 8; i++) {
        int c = tid + i * 256;
        O[off + c] = (xv[i] - mean) * inv * g[c] + b[c];
    }
}

// ---------------------------------------------------------------------------
// Embedding gather: h[s,c] = tok[ids[s],c] + pos[s,c]
// ---------------------------------------------------------------------------
__global__ __launch_bounds__(256) void embed_kernel(
    const int* __restrict__ ids, const float* __restrict__ tok,
    const float* __restrict__ pos, float* __restrict__ h)
{
    long long idx = (long long)blockIdx.x * 256 + threadIdx.x;
    int c = (int)(idx & (HD_ - 1));
    int s = (int)(idx >> 11);
    h[idx] = tok[(long long)ids[s] * HD_ + c] + pos[idx];
}

// ---------------------------------------------------------------------------
// Build packed QKV weights: Wqkv[l][k][0:256]=sum_j Wq, [256:512]=Wk, [512:768]=Wv
// ---------------------------------------------------------------------------
__global__ __launch_bounds__(256) void pack_wqkv_kernel(
    const float* __restrict__ Wq, const float* __restrict__ Wk,
    const float* __restrict__ Wv, float* __restrict__ Wqkv)
{
    long long idx = (long long)blockIdx.x * 256 + threadIdx.x;  // L*HD*768
    if (idx >= (long long)L_ * HD_ * QKV_) return;
    int col = (int)(idx % QKV_);
    long long rk = idx / QKV_;           // l*HD + k
    int k = (int)(rk & (HD_ - 1));
    int l = (int)(rk >> 11);
    float v;
    if (col < 256) {
        int gg = col >> 6, d = col & 63;
        const float* row = Wq + (((long long)l * HD_ + k) * HD_) + gg * (GS_ * D_) + d;
        float s = 0.f;
#pragma unroll
        for (int j = 0; j < GS_; j++) s += row[j * D_];
        v = s;
    } else if (col < 512) {
        v = Wk[((long long)l * HD_ + k) * GD_ + (col - 256)];
    } else {
        v = Wv[((long long)l * HD_ + k) * GD_ + (col - 512)];
    }
    Wqkv[idx] = v;
}

__global__ __launch_bounds__(256) void pack_bqkv_kernel(
    const float* __restrict__ bq, const float* __restrict__ bk,
    const float* __restrict__ bv, float* __restrict__ bqkv)
{
    int idx = blockIdx.x * 256 + threadIdx.x;   // L*768
    if (idx >= L_ * QKV_) return;
    int col = idx % QKV_;
    int l   = idx / QKV_;
    float v;
    if (col < 256) {
        int gg = col >> 6, d = col & 63;
        const float* row = bq + (long long)l * HD_ + gg * (GS_ * D_) + d;
        float s = 0.f;
#pragma unroll
        for (int j = 0; j < GS_; j++) s += row[j * D_];
        v = s;
    } else if (col < 512) {
        v = bk[(long long)l * GD_ + (col - 256)];
    } else {
        v = bv[(long long)l * GD_ + (col - 512)];
    }
    bqkv[idx] = v;
}

__global__ __launch_bounds__(256) void reduce_wo_kernel(
    const float* __restrict__ Wo, float* __restrict__ Wo_r)
{
    long long idx = (long long)blockIdx.x * 256 + threadIdx.x;
    int n  = (int)(idx & (HD_ - 1));
    int gd = (int)((idx >> 11) & (GD_ - 1));
    int l  = (int)(idx >> 19);
    int gg = gd >> 6, d = gd & 63;
    float s = 0.f;
#pragma unroll
    for (int j = 0; j < GS_; j++)
        s += Wo[(((long long)l * HD_) + gg * (GS_ * D_) + j * D_ + d) * HD_ + n];
    Wo_r[idx] = s;
}

// K transpose out of packed qkv: kt[gd][t] = qkv[t][256+gd]
__global__ __launch_bounds__(256) void transpose_k_kernel(
    const float* __restrict__ qkv, float* __restrict__ Kt)
{
    long long idx = (long long)blockIdx.x * 256 + threadIdx.x;  // GD*S
    int t  = (int)(idx & (S_ - 1));
    int gd = (int)(idx >> 10);
    Kt[idx] = qkv[(long long)t * QKV_ + 256 + gd];
}

// ---------------------------------------------------------------------------
// Host orchestration
// ---------------------------------------------------------------------------
static const int SMEM_BN128 = (2 * 128 * AP + 2 * 32 * (128 + 8)) * 4;  // 71680
static const int SMEM_BN64  = (2 * 128 * AP + 2 * 32 * (64 + 8)) * 4;   // 55296

static void launch_gemm128(int M, int N, int K, float alpha,
                           const float* A, int lda, long long sA,
                           const float* B, int ldb, long long sB,
                           const float* bias,
                           float* C, int ldc, long long sC,
                           int batch, int relu)
{
    dim3 grid(N / 128, M / 128, batch);
    tgemm_kernel<128, 64><<<grid, 128, SMEM_BN128>>>(
        M, N, K, alpha, A, lda, sA, B, ldb, sB, bias, C, ldc, sC, relu);
}

static void launch_gemm64(int M, int N, int K, float alpha,
                          const float* A, int lda, long long sA,
                          const float* B, int ldb, long long sB,
                          const float* bias,
                          float* C, int ldc, long long sC,
                          int batch, int relu)
{
    dim3 grid(N / 64, M / 128, batch);
    tgemm_kernel<64, 32><<<grid, 128, SMEM_BN64>>>(
        M, N, K, alpha, A, lda, sA, B, ldb, sB, bias, C, ldc, sC, relu);
}

extern "C" void kernel_launch(void* const* d_in, const int* in_sizes, int n_in,
                              void* d_out, int out_size)
{
    const int*   ids     = (const int*)  d_in[0];
    const float* tok_emb = (const float*)d_in[1];
    const float* pos_emb = (const float*)d_in[2];
    const float* Wq      = (const float*)d_in[3];
    const float* bq      = (const float*)d_in[4];
    const float* Wk      = (const float*)d_in[5];
    const float* bk      = (const float*)d_in[6];
    const float* Wv      = (const float*)d_in[7];
    const float* bv      = (const float*)d_in[8];
    const float* Wo      = (const float*)d_in[9];
    const float* bo      = (const float*)d_in[10];
    const float* g1      = (const float*)d_in[11];
    const float* be1     = (const float*)d_in[12];
    const float* W1      = (const float*)d_in[13];
    const float* b1      = (const float*)d_in[14];
    const float* W2      = (const float*)d_in[15];
    const float* b2      = (const float*)d_in[16];
    const float* g2      = (const float*)d_in[17];
    const float* be2     = (const float*)d_in[18];
    const float* lnf_g   = (const float*)d_in[19];
    const float* lnf_b   = (const float*)d_in[20];
    const float* Whead   = (const float*)d_in[21];
    float* out = (float*)d_out;

    static int smem_set = 0;
    if (!smem_set) {
        cudaFuncSetAttribute(tgemm_kernel<128, 64>,
                             cudaFuncAttributeMaxDynamicSharedMemorySize, SMEM_BN128);
        cudaFuncSetAttribute(tgemm_kernel<64, 32>,
                             cudaFuncAttributeMaxDynamicSharedMemorySize, SMEM_BN64);
        smem_set = 1;
    }

    float *Wqkv, *bqkv, *Wo_r, *h, *t2, *a1, *qkv, *kt, *ctx, *sc;
    cudaGetSymbolAddress((void**)&Wqkv, g_Wqkv);
    cudaGetSymbolAddress((void**)&bqkv, g_bqkv);
    cudaGetSymbolAddress((void**)&Wo_r, g_Wo_r);
    cudaGetSymbolAddress((void**)&h,    g_h);
    cudaGetSymbolAddress((void**)&t2,   g_t2);
    cudaGetSymbolAddress((void**)&a1,   g_a1);
    cudaGetSymbolAddress((void**)&qkv,  g_qkv);
    cudaGetSymbolAddress((void**)&kt,   g_kt);
    cudaGetSymbolAddress((void**)&ctx,  g_ctx);
    cudaGetSymbolAddress((void**)&sc,   g_sc);

    // weight packing / pre-reductions
    long long nwq = (long long)L_ * HD_ * QKV_;
    pack_wqkv_kernel<<<(int)((nwq + 255) / 256), 256>>>(Wq, Wk, Wv, Wqkv);
    pack_bqkv_kernel<<<(L_ * QKV_ + 255) / 256, 256>>>(bq, bk, bv, bqkv);
    reduce_wo_kernel<<<(L_ * GD_ * HD_) / 256, 256>>>(Wo, Wo_r);

    // embedding
    embed_kernel<<<(S_ * HD_) / 256, 256>>>(ids, tok_emb, pos_emb, h);

    for (int l = 0; l < L_; l++) {
        const float* Wqkv_l = Wqkv + (long long)l * HD_ * QKV_;
        const float* bqkv_l = bqkv + (long long)l * QKV_;
        const float* Wo_l   = Wo_r + (long long)l * GD_ * HD_;
        const float* bo_l   = bo   + (long long)l * HD_;
        const float* W1_l   = W1   + (long long)l * HD_ * FF_;
        const float* b1_l   = b1   + (long long)l * FF_;
        const float* W2_l   = W2   + (long long)l * FF_ * HD_;
        const float* b2_l   = b2   + (long long)l * HD_;

        // fused QKV projection  [S,HD] @ [HD,768]
        launch_gemm128(S_, QKV_, HD_, 1.f, h, HD_, 0, Wqkv_l, QKV_, 0,
                       bqkv_l, qkv, QKV_, 0, 1, 0);

        // K transpose
        transpose_k_kernel<<<(GD_ * S_) / 256, 256>>>(qkv, kt);

        // scores[g] = (1/8) * Qsum_g @ K_g^T
        launch_gemm128(S_, S_, D_, 0.125f,
                       qkv, QKV_, 64,
                       kt, S_, (long long)D_ * S_,
                       nullptr,
                       sc, S_, (long long)S_ * S_,
                       G_, 0);

        softmax_kernel<<<G_ * S_, 256>>>(sc, S_);

        // ctx[g] = attn_g @ V_g
        launch_gemm64(S_, D_, S_, 1.f,
                      sc, S_, (long long)S_ * S_,
                      qkv + 512, QKV_, 64,
                      nullptr,
                      ctx, GD_, D_,
                      G_, 0);

        // attn_out = ctx @ Wo_r + bo ; h = LN(h + attn_out)
        launch_gemm128(S_, HD_, GD_, 1.f, ctx, GD_, 0, Wo_l, HD_, 0,
                       bo_l, t2, HD_, 0, 1, 0);
        ln_kernel<<<S_, 256>>>(h, t2, g1 + (long long)l * HD_, be1 + (long long)l * HD_, h);

        // FFN
        launch_gemm128(S_, FF_, HD_, 1.f, h, HD_, 0, W1_l, FF_, 0,
                       b1_l, a1, FF_, 0, 1, 1);
        launch_gemm128(S_, HD_, FF_, 1.f, a1, FF_, 0, W2_l, HD_, 0,
                       b2_l, t2, HD_, 0, 1, 0);
        ln_kernel<<<S_, 256>>>(h, t2, g2 + (long long)l * HD_, be2 + (long long)l * HD_, h);
    }

    // final LN + lm head
    ln_kernel<<<S_, 256>>>(h, nullptr, lnf_g, lnf_b, t2);
    launch_gemm128(S_, V_, HD_, 1.f, t2, HD_, 0, Whead, V_, 0, nullptr, out, V_, 0, 1, 0);
}

// round 7
// speedup vs baseline: 4.5688x; 1.0008x over previous
#include <cuda_runtime.h>
#include <cuda_bf16.h>
#include <math.h>
#include <stdint.h>

// ---------------------------------------------------------------------------
// Problem constants
// ---------------------------------------------------------------------------
#define S_   1024
#define HD_  2048
#define L_   2
#define G_   4
#define D_   64
#define GS_  8
#define GD_  (G_ * D_)       // 256
#define QKV_ 768             // packed q(256)+k(256)+v(256)
#define FF_  8192
#define V_   38400

// ---------------------------------------------------------------------------
// Scratch (device globals -- no allocation allowed)
// ---------------------------------------------------------------------------
__device__ float g_Wqkv[L_ * HD_ * QKV_];   // packed [Wq_r | Wk | Wv]
__device__ float g_bqkv[L_ * QKV_];
__device__ float g_Wo_r[L_ * GD_ * HD_];
__device__ float g_h   [S_ * HD_];
__device__ float g_t2  [S_ * HD_];
__device__ float g_a1  [S_ * FF_];
__device__ float g_qkv [S_ * QKV_];
__device__ float g_kt  [GD_ * S_];
__device__ float g_ctx [S_ * GD_];
__device__ float g_sc  [G_ * S_ * S_];

// ---------------------------------------------------------------------------
// helpers
// ---------------------------------------------------------------------------
__device__ __forceinline__ uint32_t f2tf32(float f) {
    uint32_t r;
    asm("cvt.rna.tf32.f32 %0, %1;" : "=r"(r) : "f"(f));
    return r;
}

__device__ __forceinline__ void mma_tf32(float c[4], const uint32_t a[4], const uint32_t b[2]) {
    asm volatile(
        "mma.sync.aligned.m16n8k8.row.col.f32.tf32.tf32.f32 "
        "{%0,%1,%2,%3}, {%4,%5,%6,%7}, {%8,%9}, {%0,%1,%2,%3};"
        : "+f"(c[0]), "+f"(c[1]), "+f"(c[2]), "+f"(c[3])
        : "r"(a[0]), "r"(a[1]), "r"(a[2]), "r"(a[3]),
          "r"(b[0]), "r"(b[1]));
}

__device__ __forceinline__ void cp16(uint32_t smem_b, const float* g) {
    asm volatile("cp.async.cg.shared.global [%0], [%1], 16;\n"
                 :: "r"(smem_b), "l"(g));
}

// ---------------------------------------------------------------------------
// tf32 tensor-core GEMM, cp.async double-buffered.
// BM=128 fixed, 4 warps (2x2) of 64xWN_, BKT=32.
// A smem layout [m][k] pitch 36 words; B smem [k][n] pitch BN_+8.
// Requires: M%128==0, N%BN_==0, K%32==0, 16B-aligned rows.
// ---------------------------------------------------------------------------
#define BKT 32
#define AP  36

template<int BN_, int WN_>
__global__ __launch_bounds__(128, 2) void tgemm_kernel(
    int M, int N, int K, float alpha,
    const float* __restrict__ A, int lda, long long sA,
    const float* __restrict__ B, int ldb, long long sB,
    const float* __restrict__ bias,
    float* __restrict__ C, int ldc, long long sC,
    int relu)
{
    constexpr int BPW = BN_ + 8;
    constexpr int NI  = WN_ / 8;
    constexpr int NBV = BN_ / 16;            // B float4 vectors per thread
    constexpr int AS_WORDS = 2 * 128 * AP;   // double-buffered A
    extern __shared__ float smf[];
    float* Asm = smf;                         // [2][128][AP]
    float* Bsm = smf + AS_WORDS;              // [2][32][BPW]

    long long bz = blockIdx.z;
    A += bz * sA;
    B += bz * sB;
    C += bz * sC;

    const int row0 = blockIdx.y * 128;
    const int col0 = blockIdx.x * BN_;
    const int tid  = threadIdx.x;
    const int lane = tid & 31;
    const int warp = tid >> 5;
    const int wm   = (warp & 1) * 64;
    const int wn   = (warp >> 1) * WN_;
    const int gid  = lane >> 2;
    const int tg   = lane & 3;

    uint32_t As_b = (uint32_t)__cvta_generic_to_shared(Asm);
    uint32_t Bs_b = (uint32_t)__cvta_generic_to_shared(Bsm);

    const int T = K / BKT;

    // ---- async tile issue ----
    auto issue_tile = [&](int kt, int buf) {
        const float* Ag = A + (long long)row0 * lda + kt * BKT;
#pragma unroll
        for (int p = 0; p < 8; p++) {
            int v   = p * 128 + tid;
            int row = v >> 3;
            int ch  = (v & 7) * 4;
            cp16(As_b + (uint32_t)(((buf * 128 + row) * AP + ch) * 4),
                 Ag + (long long)row * lda + ch);
        }
        const float* Bg = B + (long long)(kt * BKT) * ldb + col0;
#pragma unroll
        for (int p = 0; p < NBV; p++) {
            int v  = p * 128 + tid;
            int kr = v / (BN_ / 4);
            int ch = (v % (BN_ / 4)) * 4;
            cp16(Bs_b + (uint32_t)(((buf * 32 + kr) * BPW + ch) * 4),
                 Bg + (long long)kr * ldb + ch);
        }
        asm volatile("cp.async.commit_group;\n" ::);
    };

    float acc[4][NI][4];
#pragma unroll
    for (int mi = 0; mi < 4; mi++)
#pragma unroll
        for (int ni = 0; ni < NI; ni++)
#pragma unroll
            for (int c = 0; c < 4; c++) acc[mi][ni][c] = 0.f;

    // prologue: 2 tiles in flight
    issue_tile(0, 0);
    issue_tile(1, 1);
    asm volatile("cp.async.wait_group 1;\n" ::);
    __syncthreads();

    for (int i = 0; i < T; i++) {
        const int buf = i & 1;
        const float* Ab = Asm + buf * 128 * AP;
        const float* Bb = Bsm + buf * 32 * BPW;

#pragma unroll
        for (int ks = 0; ks < 4; ks++) {
            const int k = ks * 8 + tg;
            uint32_t afr[4][4];
#pragma unroll
            for (int mi = 0; mi < 4; mi++) {
                int m = wm + mi * 16 + gid;
                afr[mi][0] = f2tf32(Ab[m * AP + k]);
                afr[mi][1] = f2tf32(Ab[(m + 8) * AP + k]);
                afr[mi][2] = f2tf32(Ab[m * AP + k + 4]);
                afr[mi][3] = f2tf32(Ab[(m + 8) * AP + k + 4]);
            }
            uint32_t bfr[NI][2];
#pragma unroll
            for (int ni = 0; ni < NI; ni++) {
                int n = wn + ni * 8 + gid;
                bfr[ni][0] = f2tf32(Bb[k * BPW + n]);
                bfr[ni][1] = f2tf32(Bb[(k + 4) * BPW + n]);
            }
#pragma unroll
            for (int mi = 0; mi < 4; mi++)
#pragma unroll
                for (int ni = 0; ni < NI; ni++)
                    mma_tf32(acc[mi][ni], afr[mi], bfr[ni]);
        }

        if (i + 1 < T) {
            __syncthreads();                    // all warps done with buf
            if (i + 2 < T) {
                issue_tile(i + 2, buf);
                asm volatile("cp.async.wait_group 1;\n" ::);
            } else {
                asm volatile("cp.async.wait_group 0;\n" ::);
            }
            __syncthreads();                    // tile i+1 visible everywhere
        }
    }

    // epilogue
#pragma unroll
    for (int mi = 0; mi < 4; mi++) {
        int m0 = row0 + wm + mi * 16 + gid;
#pragma unroll
        for (int ni = 0; ni < NI; ni++) {
            int n = col0 + wn + ni * 8 + tg * 2;
            float b0 = bias ? bias[n]     : 0.f;
            float b1 = bias ? bias[n + 1] : 0.f;
            float v0 = alpha * acc[mi][ni][0] + b0;
            float v1 = alpha * acc[mi][ni][1] + b1;
            float v2 = alpha * acc[mi][ni][2] + b0;
            float v3 = alpha * acc[mi][ni][3] + b1;
            if (relu) {
                v0 = fmaxf(v0, 0.f); v1 = fmaxf(v1, 0.f);
                v2 = fmaxf(v2, 0.f); v3 = fmaxf(v3, 0.f);
            }
            *(float2*)(C + (long long)m0 * ldc + n)       = make_float2(v0, v1);
            *(float2*)(C + (long long)(m0 + 8) * ldc + n) = make_float2(v2, v3);
        }
    }
}

// ---------------------------------------------------------------------------
// Softmax over rows of length T (one block per row)
// ---------------------------------------------------------------------------
__global__ __launch_bounds__(256) void softmax_kernel(float* __restrict__ Srows, int T)
{
    float* row = Srows + (long long)blockIdx.x * T;
    __shared__ float red[256];
    int tid = threadIdx.x;

    float m = -INFINITY;
    for (int i = tid; i < T; i += 256) m = fmaxf(m, row[i]);
    red[tid] = m; __syncthreads();
    for (int s = 128; s > 0; s >>= 1) {
        if (tid < s) red[tid] = fmaxf(red[tid], red[tid + s]);
        __syncthreads();
    }
    m = red[0]; __syncthreads();

    float sum = 0.f;
    for (int i = tid; i < T; i += 256) {
        float e = expf(row[i] - m);
        row[i] = e;
        sum += e;
    }
    red[tid] = sum; __syncthreads();
    for (int s = 128; s > 0; s >>= 1) {
        if (tid < s) red[tid] += red[tid + s];
        __syncthreads();
    }
    float inv = 1.f / red[0];
    for (int i = tid; i < T; i += 256) row[i] *= inv;
}

// ---------------------------------------------------------------------------
// LayerNorm with optional residual: O = LN(X + R) * g + b   (N = 2048)
// ---------------------------------------------------------------------------
__global__ __launch_bounds__(256) void ln_kernel(
    const float* __restrict__ X, const float* __restrict__ R,
    const float* __restrict__ g, const float* __restrict__ b,
    float* __restrict__ O)
{
    long long off = (long long)blockIdx.x * HD_;
    __shared__ float red[256];
    int tid = threadIdx.x;

    float xv[8];
    float lsum = 0.f;
#pragma unroll
    for (int i = 0; i < 8; i++) {
        int c = tid + i * 256;
        float x = X[off + c];
        if (R) x += R[off + c];
        xv[i] = x;
        lsum += x;
    }
    red[tid] = lsum; __syncthreads();
    for (int s = 128; s > 0; s >>= 1) {
        if (tid < s) red[tid] += red[tid + s];
        __syncthreads();
    }
    float mean = red[0] * (1.f / HD_);
    __syncthreads();

    float lvar = 0.f;
#pragma unroll
    for (int i = 0; i < 8; i++) {
        float d = xv[i] - mean;
        lvar += d * d;
    }
    red[tid] = lvar; __syncthreads();
    for (int s = 128; s > 0; s >>= 1) {
        if (tid < s) red[tid] += red[tid + s];
        __syncthreads();
    }
    float inv = rsqrtf(red[0] * (1.f / HD_) + 1e-5f);

#pragma unroll
    for (int i = 0; i < 8; i++) {
        int c = tid + i * 256;
        O[off + c] = (xv[i] - mean) * inv * g[c] + b[c];
    }
}

// ---------------------------------------------------------------------------
// Embedding gather: h[s,c] = tok[ids[s],c] + pos[s,c]
// ---------------------------------------------------------------------------
__global__ __launch_bounds__(256) void embed_kernel(
    const int* __restrict__ ids, const float* __restrict__ tok,
    const float* __restrict__ pos, float* __restrict__ h)
{
    long long idx = (long long)blockIdx.x * 256 + threadIdx.x;
    int c = (int)(idx & (HD_ - 1));
    int s = (int)(idx >> 11);
    h[idx] = tok[(long long)ids[s] * HD_ + c] + pos[idx];
}

// ---------------------------------------------------------------------------
// Build packed QKV weights: Wqkv[l][k][0:256]=sum_j Wq, [256:512]=Wk, [512:768]=Wv
// ---------------------------------------------------------------------------
__global__ __launch_bounds__(256) void pack_wqkv_kernel(
    const float* __restrict__ Wq, const float* __restrict__ Wk,
    const float* __restrict__ Wv, float* __restrict__ Wqkv)
{
    long long idx = (long long)blockIdx.x * 256 + threadIdx.x;  // L*HD*768
    if (idx >= (long long)L_ * HD_ * QKV_) return;
    int col = (int)(idx % QKV_);
    long long rk = idx / QKV_;           // l*HD + k
    int k = (int)(rk & (HD_ - 1));
    int l = (int)(rk >> 11);
    float v;
    if (col < 256) {
        int gg = col >> 6, d = col & 63;
        const float* row = Wq + (((long long)l * HD_ + k) * HD_) + gg * (GS_ * D_) + d;
        float s = 0.f;
#pragma unroll
        for (int j = 0; j < GS_; j++) s += row[j * D_];
        v = s;
    } else if (col < 512) {
        v = Wk[((long long)l * HD_ + k) * GD_ + (col - 256)];
    } else {
        v = Wv[((long long)l * HD_ + k) * GD_ + (col - 512)];
    }
    Wqkv[idx] = v;
}

__global__ __launch_bounds__(256) void pack_bqkv_kernel(
    const float* __restrict__ bq, const float* __restrict__ bk,
    const float* __restrict__ bv, float* __restrict__ bqkv)
{
    int idx = blockIdx.x * 256 + threadIdx.x;   // L*768
    if (idx >= L_ * QKV_) return;
    int col = idx % QKV_;
    int l   = idx / QKV_;
    float v;
    if (col < 256) {
        int gg = col >> 6, d = col & 63;
        const float* row = bq + (long long)l * HD_ + gg * (GS_ * D_) + d;
        float s = 0.f;
#pragma unroll
        for (int j = 0; j < GS_; j++) s += row[j * D_];
        v = s;
    } else if (col < 512) {
        v = bk[(long long)l * GD_ + (col - 256)];
    } else {
        v = bv[(long long)l * GD_ + (col - 512)];
    }
    bqkv[idx] = v;
}

__global__ __launch_bounds__(256) void reduce_wo_kernel(
    const float* __restrict__ Wo, float* __restrict__ Wo_r)
{
    long long idx = (long long)blockIdx.x * 256 + threadIdx.x;
    int n  = (int)(idx & (HD_ - 1));
    int gd = (int)((idx >> 11) & (GD_ - 1));
    int l  = (int)(idx >> 19);
    int gg = gd >> 6, d = gd & 63;
    float s = 0.f;
#pragma unroll
    for (int j = 0; j < GS_; j++)
        s += Wo[(((long long)l * HD_) + gg * (GS_ * D_) + j * D_ + d) * HD_ + n];
    Wo_r[idx] = s;
}

// K transpose out of packed qkv: kt[gd][t] = qkv[t][256+gd]
__global__ __launch_bounds__(256) void transpose_k_kernel(
    const float* __restrict__ qkv, float* __restrict__ Kt)
{
    long long idx = (long long)blockIdx.x * 256 + threadIdx.x;  // GD*S
    int t  = (int)(idx & (S_ - 1));
    int gd = (int)(idx >> 10);
    Kt[idx] = qkv[(long long)t * QKV_ + 256 + gd];
}

// ---------------------------------------------------------------------------
// Host orchestration
// ---------------------------------------------------------------------------
static const int SMEM_BN128 = (2 * 128 * AP + 2 * 32 * (128 + 8)) * 4;  // 71680
static const int SMEM_BN64  = (2 * 128 * AP + 2 * 32 * (64 + 8)) * 4;   // 55296

static void launch_gemm128(int M, int N, int K, float alpha,
                           const float* A, int lda, long long sA,
                           const float* B, int ldb, long long sB,
                           const float* bias,
                           float* C, int ldc, long long sC,
                           int batch, int relu)
{
    dim3 grid(N / 128, M / 128, batch);
    tgemm_kernel<128, 64><<<grid, 128, SMEM_BN128>>>(
        M, N, K, alpha, A, lda, sA, B, ldb, sB, bias, C, ldc, sC, relu);
}

static void launch_gemm64(int M, int N, int K, float alpha,
                          const float* A, int lda, long long sA,
                          const float* B, int ldb, long long sB,
                          const float* bias,
                          float* C, int ldc, long long sC,
                          int batch, int relu)
{
    dim3 grid(N / 64, M / 128, batch);
    tgemm_kernel<64, 32><<<grid, 128, SMEM_BN64>>>(
        M, N, K, alpha, A, lda, sA, B, ldb, sB, bias, C, ldc, sC, relu);
}

extern "C" void kernel_launch(void* const* d_in, const int* in_sizes, int n_in,
                              void* d_out, int out_size)
{
    const int*   ids     = (const int*)  d_in[0];
    const float* tok_emb = (const float*)d_in[1];
    const float* pos_emb = (const float*)d_in[2];
    const float* Wq      = (const float*)d_in[3];
    const float* bq      = (const float*)d_in[4];
    const float* Wk      = (const float*)d_in[5];
    const float* bk      = (const float*)d_in[6];
    const float* Wv      = (const float*)d_in[7];
    const float* bv      = (const float*)d_in[8];
    const float* Wo      = (const float*)d_in[9];
    const float* bo      = (const float*)d_in[10];
    const float* g1      = (const float*)d_in[11];
    const float* be1     = (const float*)d_in[12];
    const float* W1      = (const float*)d_in[13];
    const float* b1      = (const float*)d_in[14];
    const float* W2      = (const float*)d_in[15];
    const float* b2      = (const float*)d_in[16];
    const float* g2      = (const float*)d_in[17];
    const float* be2     = (const float*)d_in[18];
    const float* lnf_g   = (const float*)d_in[19];
    const float* lnf_b   = (const float*)d_in[20];
    const float* Whead   = (const float*)d_in[21];
    float* out = (float*)d_out;

    static int smem_set = 0;
    if (!smem_set) {
        cudaFuncSetAttribute(tgemm_kernel<128, 64>,
                             cudaFuncAttributeMaxDynamicSharedMemorySize, SMEM_BN128);
        cudaFuncSetAttribute(tgemm_kernel<64, 32>,
                             cudaFuncAttributeMaxDynamicSharedMemorySize, SMEM_BN64);
        smem_set = 1;
    }

    float *Wqkv, *bqkv, *Wo_r, *h, *t2, *a1, *qkv, *kt, *ctx, *sc;
    cudaGetSymbolAddress((void**)&Wqkv, g_Wqkv);
    cudaGetSymbolAddress((void**)&bqkv, g_bqkv);
    cudaGetSymbolAddress((void**)&Wo_r, g_Wo_r);
    cudaGetSymbolAddress((void**)&h,    g_h);
    cudaGetSymbolAddress((void**)&t2,   g_t2);
    cudaGetSymbolAddress((void**)&a1,   g_a1);
    cudaGetSymbolAddress((void**)&qkv,  g_qkv);
    cudaGetSymbolAddress((void**)&kt,   g_kt);
    cudaGetSymbolAddress((void**)&ctx,  g_ctx);
    cudaGetSymbolAddress((void**)&sc,   g_sc);

    // weight packing / pre-reductions
    long long nwq = (long long)L_ * HD_ * QKV_;
    pack_wqkv_kernel<<<(int)((nwq + 255) / 256), 256>>>(Wq, Wk, Wv, Wqkv);
    pack_bqkv_kernel<<<(L_ * QKV_ + 255) / 256, 256>>>(bq, bk, bv, bqkv);
    reduce_wo_kernel<<<(L_ * GD_ * HD_) / 256, 256>>>(Wo, Wo_r);

    // embedding
    embed_kernel<<<(S_ * HD_) / 256, 256>>>(ids, tok_emb, pos_emb, h);

    for (int l = 0; l < L_; l++) {
        const float* Wqkv_l = Wqkv + (long long)l * HD_ * QKV_;
        const float* bqkv_l = bqkv + (long long)l * QKV_;
        const float* Wo_l   = Wo_r + (long long)l * GD_ * HD_;
        const float* bo_l   = bo   + (long long)l * HD_;
        const float* W1_l   = W1   + (long long)l * HD_ * FF_;
        const float* b1_l   = b1   + (long long)l * FF_;
        const float* W2_l   = W2   + (long long)l * FF_ * HD_;
        const float* b2_l   = b2   + (long long)l * HD_;

        // fused QKV projection  [S,HD] @ [HD,768]
        launch_gemm128(S_, QKV_, HD_, 1.f, h, HD_, 0, Wqkv_l, QKV_, 0,
                       bqkv_l, qkv, QKV_, 0, 1, 0);

        // K transpose
        transpose_k_kernel<<<(GD_ * S_) / 256, 256>>>(qkv, kt);

        // scores[g] = (1/8) * Qsum_g @ K_g^T
        launch_gemm128(S_, S_, D_, 0.125f,
                       qkv, QKV_, 64,
                       kt, S_, (long long)D_ * S_,
                       nullptr,
                       sc, S_, (long long)S_ * S_,
                       G_, 0);

        softmax_kernel<<<G_ * S_, 256>>>(sc, S_);

        // ctx[g] = attn_g @ V_g
        launch_gemm64(S_, D_, S_, 1.f,
                      sc, S_, (long long)S_ * S_,
                      qkv + 512, QKV_, 64,
                      nullptr,
                      ctx, GD_, D_,
                      G_, 0);

        // attn_out = ctx @ Wo_r + bo ; h = LN(h + attn_out)
        launch_gemm128(S_, HD_, GD_, 1.f, ctx, GD_, 0, Wo_l, HD_, 0,
                       bo_l, t2, HD_, 0, 1, 0);
        ln_kernel<<<S_, 256>>>(h, t2, g1 + (long long)l * HD_, be1 + (long long)l * HD_, h);

        // FFN
        launch_gemm128(S_, FF_, HD_, 1.f, h, HD_, 0, W1_l, FF_, 0,
                       b1_l, a1, FF_, 0, 1, 1);
        launch_gemm128(S_, HD_, FF_, 1.f, a1, FF_, 0, W2_l, HD_, 0,
                       b2_l, t2, HD_, 0, 1, 0);
        ln_kernel<<<S_, 256>>>(h, t2, g2 + (long long)l * HD_, be2 + (long long)l * HD_, h);
    }

    // final LN + lm head
    ln_kernel<<<S_, 256>>>(h, nullptr, lnf_g, lnf_b, t2);
    launch_gemm128(S_, V_, HD_, 1.f, t2, HD_, 0, Whead, V_, 0, nullptr, out, V_, 0, 1, 0);
}

// round 9
// speedup vs baseline: 5.5346x; 1.2114x over previous
#include <cuda_runtime.h>
#include <cuda_bf16.h>
#include <math.h>
#include <stdint.h>

#define S_   1024
#define HD_  2048
#define L_   2
#define G_   4
#define D_   64
#define GS_  8
#define GD_  256
#define QKV_ 768
#define FF_  8192
#define V_   38400

// ---------------- scratch ----------------
__device__ float g_Wqkv[L_ * HD_ * QKV_];
__device__ float g_bqkv[L_ * QKV_];
__device__ float g_Wo_r[L_ * GD_ * HD_];
__device__ float g_h   [S_ * HD_];
__device__ float g_htf [S_ * HD_];
__device__ float g_t2  [S_ * HD_];
__device__ float g_a1  [S_ * FF_];
__device__ float g_qkv [S_ * QKV_];
__device__ float g_vt  [GD_ * S_];
__device__ float g_ctx [S_ * GD_];
__device__ float g_sc  [G_ * S_ * S_];
__device__ float g_WqkvT[L_ * QKV_ * HD_];
__device__ float g_WoT  [L_ * HD_ * GD_];
__device__ float g_W1T  [L_ * FF_ * HD_];
__device__ float g_W2T  [L_ * HD_ * FF_];
__device__ float g_WheadT[(long long)V_ * HD_];

// ---------------- helpers ----------------
__device__ __forceinline__ uint32_t f2tf32(float f) {
    uint32_t r; asm("cvt.rna.tf32.f32 %0, %1;" : "=r"(r) : "f"(f)); return r;
}
__device__ __forceinline__ float rtf(float f) { return __uint_as_float(f2tf32(f)); }
__device__ __forceinline__ void cp16(uint32_t d, const float* g) {
    asm volatile("cp.async.cg.shared.global [%0], [%1], 16;\n" :: "r"(d), "l"(g));
}
__device__ __forceinline__ void ldx4(uint32_t* r, uint32_t addr) {
    asm volatile("ldmatrix.sync.aligned.m8n8.x4.shared.b16 {%0,%1,%2,%3}, [%4];"
                 : "=r"(r[0]), "=r"(r[1]), "=r"(r[2]), "=r"(r[3]) : "r"(addr));
}
__device__ __forceinline__ void mma_tf32(float c[4], const uint32_t a[4], const uint32_t b[2]) {
    asm volatile(
        "mma.sync.aligned.m16n8k8.row.col.f32.tf32.tf32.f32 "
        "{%0,%1,%2,%3}, {%4,%5,%6,%7}, {%8,%9}, {%0,%1,%2,%3};"
        : "+f"(c[0]), "+f"(c[1]), "+f"(c[2]), "+f"(c[3])
        : "r"(a[0]), "r"(a[1]), "r"(a[2]), "r"(a[3]), "r"(b[0]), "r"(b[1]));
}

// ---------------------------------------------------------------------------
// tf32 GEMM via ldmatrix-fed mma.sync.
//   C[M,N] = alpha * A[M,K] @ Bt[N,K]^T (+bias)
// A,Bt fp32 holding tf32-rounded values (k-contiguous rows, 16B aligned,
// K multiple of 32, M mult of 128, N mult of BN_).
// Block 128x BN_ x32, 128 threads (2x2 warps of 64 x BN_/2).
// smem: rows of 128B (32 tf32), XOR-swizzled (chunk ^= row&7) so both
// cp.async 16B stores and 8-row ldmatrix reads are conflict-free.
// flags: 1=relu, 2=tf32-round output, 4=atomicAdd
// ---------------------------------------------------------------------------
template<int BN_>
__global__ __launch_bounds__(128, 2) void gemm_ldm(
    const float* __restrict__ A, long long lda, long long sA,
    const float* __restrict__ Bt, long long ldb, long long sB,
    const float* __restrict__ bias,
    float* __restrict__ C, long long ldc, long long sC,
    int kchunks, long long kbz, float alpha, int flags)
{
    constexpr int NI = BN_ / 16;              // MMA n-frags per warp (8 or 4)
    constexpr int ABYTES = 128 * 128;         // A: 128 rows x 128B
    constexpr int STAGE  = ABYTES + BN_ * 128;
    extern __shared__ char dsm[];
    const uint32_t base = (uint32_t)__cvta_generic_to_shared(dsm);

    const long long bz = blockIdx.z;
    A  += bz * sA;
    Bt += bz * sB;
    C  += bz * sC;
    const long long kb = bz * kbz;

    const int tid  = threadIdx.x;
    const int lane = tid & 31;
    const int warp = tid >> 5;
    const int wm   = (warp & 1) * 64;
    const int wn   = (warp >> 1) * (BN_ / 2);
    const int gid  = lane >> 2;
    const int tg   = lane & 3;
    const int row0 = blockIdx.y * 128;
    const int col0 = blockIdx.x * BN_;

    // ldmatrix per-thread row/chunk assignments
    const int rowA = lane & 15;               // lanes16-31 reuse rows, next chunk
    const int acb  = (lane >> 4) & 1;
    const int rowB = (lane & 7) + ((lane >> 4) << 3);
    const int bcb  = (lane >> 3) & 1;
    const uint32_t amask = (uint32_t)(rowA & 7);
    const uint32_t bmask = (uint32_t)(rowB & 7);

    const int T = kchunks;

    auto load_chunk = [&](int i, int buf) {
        const long long k0 = kb + (long long)i * 32;
        const uint32_t sb = base + buf * STAGE;
#pragma unroll
        for (int p = 0; p < 8; p++) {                       // A: 1024 chunks
            int v = p * 128 + tid;
            int row = v >> 3, ch = v & 7;
            cp16(sb + (uint32_t)(row * 128 + ((ch ^ (row & 7)) << 4)),
                 A + (long long)(row0 + row) * lda + k0 + ch * 4);
        }
#pragma unroll
        for (int p = 0; p < BN_ / 16; p++) {                // B: BN_*8 chunks
            int v = p * 128 + tid;
            int row = v >> 3, ch = v & 7;
            cp16(sb + (uint32_t)(ABYTES + row * 128 + ((ch ^ (row & 7)) << 4)),
                 Bt + (long long)(col0 + row) * ldb + k0 + ch * 4);
        }
        asm volatile("cp.async.commit_group;\n" ::);
    };

    float acc[4][NI][4];
#pragma unroll
    for (int mi = 0; mi < 4; mi++)
#pragma unroll
        for (int ni = 0; ni < NI; ni++)
#pragma unroll
            for (int c = 0; c < 4; c++) acc[mi][ni][c] = 0.f;

    load_chunk(0, 0);
    if (T > 1) load_chunk(1, 1);
    asm volatile("cp.async.wait_group 1;\n" ::);
    __syncthreads();

    for (int i = 0; i < T; i++) {
        const int buf = i & 1;
        const uint32_t Ab = base + buf * STAGE;
        const uint32_t Bb = Ab + ABYTES;

#pragma unroll
        for (int ks = 0; ks < 4; ks++) {
            const uint32_t ca = (uint32_t)(ks * 2 + acb);
            const uint32_t cb = (uint32_t)(ks * 2 + bcb);
            uint32_t afr[4][4];
#pragma unroll
            for (int mi = 0; mi < 4; mi++) {
                uint32_t r = (uint32_t)(wm + mi * 16 + rowA);
                ldx4(afr[mi], Ab + r * 128 + ((ca ^ amask) << 4));
            }
            uint32_t bfr[NI][2];
#pragma unroll
            for (int p = 0; p < NI / 2; p++) {
                uint32_t r = (uint32_t)(wn + p * 16 + rowB);
                uint32_t q[4];
                ldx4(q, Bb + r * 128 + ((cb ^ bmask) << 4));
                bfr[2 * p][0] = q[0]; bfr[2 * p][1] = q[1];
                bfr[2 * p + 1][0] = q[2]; bfr[2 * p + 1][1] = q[3];
            }
#pragma unroll
            for (int mi = 0; mi < 4; mi++)
#pragma unroll
                for (int ni = 0; ni < NI; ni++)
                    mma_tf32(acc[mi][ni], afr[mi], bfr[ni]);
        }

        if (i + 1 < T) {
            __syncthreads();
            if (i + 2 < T) {
                load_chunk(i + 2, buf);
                asm volatile("cp.async.wait_group 1;\n" ::);
            } else {
                asm volatile("cp.async.wait_group 0;\n" ::);
            }
            __syncthreads();
        }
    }

    // epilogue
#pragma unroll
    for (int mi = 0; mi < 4; mi++) {
        int m0 = row0 + wm + mi * 16 + gid;
#pragma unroll
        for (int ni = 0; ni < NI; ni++) {
            int n = col0 + wn + ni * 8 + tg * 2;
            float v0 = alpha * acc[mi][ni][0];
            float v1 = alpha * acc[mi][ni][1];
            float v2 = alpha * acc[mi][ni][2];
            float v3 = alpha * acc[mi][ni][3];
            if (flags & 4) {
                atomicAdd(C + (long long)m0 * ldc + n, v0);
                atomicAdd(C + (long long)m0 * ldc + n + 1, v1);
                atomicAdd(C + (long long)(m0 + 8) * ldc + n, v2);
                atomicAdd(C + (long long)(m0 + 8) * ldc + n + 1, v3);
            } else {
                if (bias) {
                    float b0 = bias[n], b1 = bias[n + 1];
                    v0 += b0; v1 += b1; v2 += b0; v3 += b1;
                }
                if (flags & 1) {
                    v0 = fmaxf(v0, 0.f); v1 = fmaxf(v1, 0.f);
                    v2 = fmaxf(v2, 0.f); v3 = fmaxf(v3, 0.f);
                }
                if (flags & 2) { v0 = rtf(v0); v1 = rtf(v1); v2 = rtf(v2); v3 = rtf(v3); }
                *(float2*)(C + (long long)m0 * ldc + n)       = make_float2(v0, v1);
                *(float2*)(C + (long long)(m0 + 8) * ldc + n) = make_float2(v2, v3);
            }
        }
    }
}

// ---------------- elementwise kernels ----------------
__global__ __launch_bounds__(256) void softmax_kernel(float* __restrict__ Srows, int T)
{
    float* row = Srows + (long long)blockIdx.x * T;
    __shared__ float red[256];
    int tid = threadIdx.x;
    float m = -INFINITY;
    for (int i = tid; i < T; i += 256) m = fmaxf(m, row[i]);
    red[tid] = m; __syncthreads();
    for (int s = 128; s > 0; s >>= 1) { if (tid < s) red[tid] = fmaxf(red[tid], red[tid + s]); __syncthreads(); }
    m = red[0]; __syncthreads();
    float sum = 0.f;
    for (int i = tid; i < T; i += 256) { float e = expf(row[i] - m); row[i] = e; sum += e; }
    red[tid] = sum; __syncthreads();
    for (int s = 128; s > 0; s >>= 1) { if (tid < s) red[tid] += red[tid + s]; __syncthreads(); }
    float inv = 1.f / red[0];
    for (int i = tid; i < T; i += 256) row[i] = rtf(row[i] * inv);
}

__global__ __launch_bounds__(256) void ln_kernel(
    const float* __restrict__ X, const float* __restrict__ R,
    const float* __restrict__ g, const float* __restrict__ b,
    float* __restrict__ O, float* __restrict__ O2)
{
    long long off = (long long)blockIdx.x * HD_;
    __shared__ float red[256];
    int tid = threadIdx.x;
    float xv[8];
    float lsum = 0.f;
#pragma unroll
    for (int i = 0; i < 8; i++) {
        int c = tid + i * 256;
        float x = X[off + c];
        if (R) x += R[off + c];
        xv[i] = x; lsum += x;
    }
    red[tid] = lsum; __syncthreads();
    for (int s = 128; s > 0; s >>= 1) { if (tid < s) red[tid] += red[tid + s]; __syncthreads(); }
    float mean = red[0] * (1.f / HD_);
    __syncthreads();
    float lvar = 0.f;
#pragma unroll
    for (int i = 0; i < 8; i++) { float d = xv[i] - mean; lvar += d * d; }
    red[tid] = lvar; __syncthreads();
    for (int s = 128; s > 0; s >>= 1) { if (tid < s) red[tid] += red[tid + s]; __syncthreads(); }
    float inv = rsqrtf(red[0] * (1.f / HD_) + 1e-5f);
#pragma unroll
    for (int i = 0; i < 8; i++) {
        int c = tid + i * 256;
        float o = (xv[i] - mean) * inv * g[c] + b[c];
        O[off + c] = o;
        if (O2) O2[off + c] = rtf(o);
    }
}

__global__ __launch_bounds__(256) void embed_kernel(
    const int* __restrict__ ids, const float* __restrict__ tok,
    const float* __restrict__ pos, float* __restrict__ h, float* __restrict__ htf)
{
    long long idx = (long long)blockIdx.x * 256 + threadIdx.x;
    int c = (int)(idx & (HD_ - 1));
    int s = (int)(idx >> 11);
    float v = tok[(long long)ids[s] * HD_ + c] + pos[idx];
    h[idx] = v;
    htf[idx] = rtf(v);
}

__global__ __launch_bounds__(256) void init_bias_kernel(
    const float* __restrict__ b, float* __restrict__ o)
{
    long long idx = (long long)blockIdx.x * 256 + threadIdx.x;
    o[idx] = b[idx & (HD_ - 1)];
}

__global__ __launch_bounds__(256) void pack_wqkv_kernel(
    const float* __restrict__ Wq, const float* __restrict__ Wk,
    const float* __restrict__ Wv, float* __restrict__ Wqkv)
{
    long long idx = (long long)blockIdx.x * 256 + threadIdx.x;
    if (idx >= (long long)L_ * HD_ * QKV_) return;
    int col = (int)(idx % QKV_);
    long long rk = idx / QKV_;
    int k = (int)(rk & (HD_ - 1));
    int l = (int)(rk >> 11);
    float v;
    if (col < 256) {
        int gg = col >> 6, d = col & 63;
        const float* row = Wq + (((long long)l * HD_ + k) * HD_) + gg * (GS_ * D_) + d;
        float s = 0.f;
#pragma unroll
        for (int j = 0; j < GS_; j++) s += row[j * D_];
        v = s;
    } else if (col < 512) {
        v = Wk[((long long)l * HD_ + k) * GD_ + (col - 256)];
    } else {
        v = Wv[((long long)l * HD_ + k) * GD_ + (col - 512)];
    }
    Wqkv[idx] = v;
}

__global__ __launch_bounds__(256) void pack_bqkv_kernel(
    const float* __restrict__ bq, const float* __restrict__ bk,
    const float* __restrict__ bv, float* __restrict__ bqkv)
{
    int idx = blockIdx.x * 256 + threadIdx.x;
    if (idx >= L_ * QKV_) return;
    int col = idx % QKV_;
    int l = idx / QKV_;
    float v;
    if (col < 256) {
        int gg = col >> 6, d = col & 63;
        const float* row = bq + (long long)l * HD_ + gg * (GS_ * D_) + d;
        float s = 0.f;
#pragma unroll
        for (int j = 0; j < GS_; j++) s += row[j * D_];
        v = s;
    } else if (col < 512) v = bk[(long long)l * GD_ + (col - 256)];
    else v = bv[(long long)l * GD_ + (col - 512)];
    bqkv[idx] = v;
}

__global__ __launch_bounds__(256) void reduce_wo_kernel(
    const float* __restrict__ Wo, float* __restrict__ Wo_r)
{
    long long idx = (long long)blockIdx.x * 256 + threadIdx.x;
    int n = (int)(idx & (HD_ - 1));
    int gd = (int)((idx >> 11) & (GD_ - 1));
    int l = (int)(idx >> 19);
    int gg = gd >> 6, d = gd & 63;
    float s = 0.f;
#pragma unroll
    for (int j = 0; j < GS_; j++)
        s += Wo[(((long long)l * HD_) + gg * (GS_ * D_) + j * D_ + d) * HD_ + n];
    Wo_r[idx] = s;
}

// [R][C] -> [C][R] with tf32 rounding (dense)
__global__ __launch_bounds__(256) void transpose_round_kernel(
    const float* __restrict__ src, float* __restrict__ dst, int R, int C)
{
    __shared__ float t[32][33];
    int r0 = blockIdx.y * 32, c0 = blockIdx.x * 32;
    int tx = threadIdx.x & 31, ty = threadIdx.x >> 5;
#pragma unroll
    for (int j = 0; j < 4; j++)
        t[ty + j * 8][tx] = src[(long long)(r0 + ty + j * 8) * C + c0 + tx];
    __syncthreads();
#pragma unroll
    for (int j = 0; j < 4; j++)
        dst[(long long)(c0 + ty + j * 8) * R + r0 + tx] = rtf(t[tx][ty + j * 8]);
}

// vt[gd][t] = qkv[t][512+gd]   (V already rounded)
__global__ __launch_bounds__(256) void transpose_v_kernel(
    const float* __restrict__ qkv, float* __restrict__ vt)
{
    __shared__ float t[32][33];
    int c0 = blockIdx.x * 32;   // gd
    int r0 = blockIdx.y * 32;   // t
    int tx = threadIdx.x & 31, ty = threadIdx.x >> 5;
#pragma unroll
    for (int j = 0; j < 4; j++)
        t[ty + j * 8][tx] = qkv[(long long)(r0 + ty + j * 8) * QKV_ + 512 + c0 + tx];
    __syncthreads();
#pragma unroll
    for (int j = 0; j < 4; j++)
        vt[(long long)(c0 + ty + j * 8) * S_ + r0 + tx] = t[tx][ty + j * 8];
}

// ---------------- host ----------------
static const int SMEM_128 = 2 * (128 + 128) * 128;   // 65536
static const int SMEM_64  = 2 * (128 + 64) * 128;    // 49152

extern "C" void kernel_launch(void* const* d_in, const int* in_sizes, int n_in,
                              void* d_out, int out_size)
{
    const int*   ids     = (const int*)  d_in[0];
    const float* tok_emb = (const float*)d_in[1];
    const float* pos_emb = (const float*)d_in[2];
    const float* Wq  = (const float*)d_in[3];
    const float* bq  = (const float*)d_in[4];
    const float* Wk  = (const float*)d_in[5];
    const float* bk  = (const float*)d_in[6];
    const float* Wv  = (const float*)d_in[7];
    const float* bv  = (const float*)d_in[8];
    const float* Wo  = (const float*)d_in[9];
    const float* bo  = (const float*)d_in[10];
    const float* g1  = (const float*)d_in[11];
    const float* be1 = (const float*)d_in[12];
    const float* W1  = (const float*)d_in[13];
    const float* b1  = (const float*)d_in[14];
    const float* W2  = (const float*)d_in[15];
    const float* b2  = (const float*)d_in[16];
    const float* g2  = (const float*)d_in[17];
    const float* be2 = (const float*)d_in[18];
    const float* lnf_g = (const float*)d_in[19];
    const float* lnf_b = (const float*)d_in[20];
    const float* Whead = (const float*)d_in[21];
    float* out = (float*)d_out;

    cudaFuncSetAttribute(gemm_ldm<128>, cudaFuncAttributeMaxDynamicSharedMemorySize, SMEM_128);
    cudaFuncSetAttribute(gemm_ldm<64>,  cudaFuncAttributeMaxDynamicSharedMemorySize, SMEM_64);

    float *Wqkv, *bqkv, *Wo_r, *h, *htf, *t2, *a1, *qkv, *vt, *ctx, *sc;
    float *WqkvT, *WoT, *W1T, *W2T, *WheadT;
    cudaGetSymbolAddress((void**)&Wqkv, g_Wqkv);
    cudaGetSymbolAddress((void**)&bqkv, g_bqkv);
    cudaGetSymbolAddress((void**)&Wo_r, g_Wo_r);
    cudaGetSymbolAddress((void**)&h,    g_h);
    cudaGetSymbolAddress((void**)&htf,  g_htf);
    cudaGetSymbolAddress((void**)&t2,   g_t2);
    cudaGetSymbolAddress((void**)&a1,   g_a1);
    cudaGetSymbolAddress((void**)&qkv,  g_qkv);
    cudaGetSymbolAddress((void**)&vt,   g_vt);
    cudaGetSymbolAddress((void**)&ctx,  g_ctx);
    cudaGetSymbolAddress((void**)&sc,   g_sc);
    cudaGetSymbolAddress((void**)&WqkvT, g_WqkvT);
    cudaGetSymbolAddress((void**)&WoT,   g_WoT);
    cudaGetSymbolAddress((void**)&W1T,   g_W1T);
    cudaGetSymbolAddress((void**)&W2T,   g_W2T);
    cudaGetSymbolAddress((void**)&WheadT, g_WheadT);

    // ---- weight prep: pack, reduce, transpose to [n][k] tf32 ----
    long long nwq = (long long)L_ * HD_ * QKV_;
    pack_wqkv_kernel<<<(int)((nwq + 255) / 256), 256>>>(Wq, Wk, Wv, Wqkv);
    pack_bqkv_kernel<<<(L_ * QKV_ + 255) / 256, 256>>>(bq, bk, bv, bqkv);
    reduce_wo_kernel<<<(L_ * GD_ * HD_) / 256, 256>>>(Wo, Wo_r);
    for (int l = 0; l < L_; l++) {
        transpose_round_kernel<<<dim3(QKV_ / 32, HD_ / 32), 256>>>(
            Wqkv + (long long)l * HD_ * QKV_, WqkvT + (long long)l * QKV_ * HD_, HD_, QKV_);
        transpose_round_kernel<<<dim3(HD_ / 32, GD_ / 32), 256>>>(
            Wo_r + (long long)l * GD_ * HD_, WoT + (long long)l * HD_ * GD_, GD_, HD_);
        transpose_round_kernel<<<dim3(FF_ / 32, HD_ / 32), 256>>>(
            W1 + (long long)l * HD_ * FF_, W1T + (long long)l * FF_ * HD_, HD_, FF_);
        transpose_round_kernel<<<dim3(HD_ / 32, FF_ / 32), 256>>>(
            W2 + (long long)l * FF_ * HD_, W2T + (long long)l * HD_ * FF_, FF_, HD_);
    }
    transpose_round_kernel<<<dim3(V_ / 32, HD_ / 32), 256>>>(Whead, WheadT, HD_, V_);

    embed_kernel<<<(S_ * HD_) / 256, 256>>>(ids, tok_emb, pos_emb, h, htf);

    for (int l = 0; l < L_; l++) {
        const float* WqkvT_l = WqkvT + (long long)l * QKV_ * HD_;
        const float* bqkv_l  = bqkv  + (long long)l * QKV_;
        const float* WoT_l   = WoT   + (long long)l * HD_ * GD_;
        const float* W1T_l   = W1T   + (long long)l * FF_ * HD_;
        const float* W2T_l   = W2T   + (long long)l * HD_ * FF_;

        // QKV projection: [1024,2048] @ [2048,768]
        gemm_ldm<128><<<dim3(QKV_ / 128, S_ / 128, 1), 128, SMEM_128>>>(
            htf, HD_, 0, WqkvT_l, HD_, 0, bqkv_l, qkv, QKV_, 0,
            HD_ / 32, 0, 1.f, 2);

        transpose_v_kernel<<<dim3(GD_ / 32, S_ / 32), 256>>>(qkv, vt);

        // scores[g] = 1/8 * Q_g @ K_g^T  (K rows are already [t][d])
        gemm_ldm<128><<<dim3(S_ / 128, S_ / 128, G_), 128, SMEM_128>>>(
            qkv, QKV_, 64, qkv + 256, QKV_, 64, nullptr,
            sc, S_, (long long)S_ * S_, 64 / 32, 0, 0.125f, 0);

        softmax_kernel<<<G_ * S_, 256>>>(sc, S_);

        // ctx[g] = attn_g @ V_g   (B = vt[g] in [d][t])
        gemm_ldm<64><<<dim3(1, S_ / 128, G_), 128, SMEM_64>>>(
            sc, S_, (long long)S_ * S_, vt, S_, (long long)D_ * S_, nullptr,
            ctx, GD_, 64, S_ / 32, 0, 1.f, 2);

        // attn_out = ctx @ Wo_r + bo ; h = LN(h + attn_out)
        gemm_ldm<128><<<dim3(HD_ / 128, S_ / 128, 1), 128, SMEM_128>>>(
            ctx, GD_, 0, WoT_l, GD_, 0, bo + (long long)l * HD_,
            t2, HD_, 0, GD_ / 32, 0, 1.f, 0);
        ln_kernel<<<S_, 256>>>(h, t2, g1 + (long long)l * HD_, be1 + (long long)l * HD_, h, htf);

        // FFN: W1 (relu), then W2 with ksplit=2 into bias-pre-initialized t2
        gemm_ldm<128><<<dim3(FF_ / 128, S_ / 128, 1), 128, SMEM_128>>>(
            htf, HD_, 0, W1T_l, HD_, 0, b1 + (long long)l * FF_,
            a1, FF_, 0, HD_ / 32, 0, 1.f, 1 | 2);
        init_bias_kernel<<<(S_ * HD_) / 256, 256>>>(b2 + (long long)l * HD_, t2);
        gemm_ldm<128><<<dim3(HD_ / 128, S_ / 128, 2), 128, SMEM_128>>>(
            a1, FF_, 0, W2T_l, FF_, 0, nullptr,
            t2, HD_, 0, FF_ / 32 / 2, (long long)(FF_ / 2), 1.f, 4);
        ln_kernel<<<S_, 256>>>(h, t2, g2 + (long long)l * HD_, be2 + (long long)l * HD_, h, htf);
    }

    // final LN (rounded into a1) + lm head
    ln_kernel<<<S_, 256>>>(h, nullptr, lnf_g, lnf_b, t2, a1);
    gemm_ldm<128><<<dim3(V_ / 128, S_ / 128, 1), 128, SMEM_128>>>(
        a1, HD_, 0, WheadT, HD_, 0, nullptr,
        out, V_, 0, HD_ / 32, 0, 1.f, 0);
}

// round 11
// speedup vs baseline: 5.5451x; 1.0019x over previous
#include <cuda_runtime.h>
#include <cuda_bf16.h>
#include <math.h>
#include <stdint.h>

#define S_   1024
#define HD_  2048
#define L_   2
#define G_   4
#define D_   64
#define GS_  8
#define GD_  256
#define QKV_ 768
#define FF_  8192
#define V_   38400

// ---------------- scratch ----------------
__device__ float g_Wqkv[L_ * HD_ * QKV_];
__device__ float g_bqkv[L_ * QKV_];
__device__ float g_Wo_r[L_ * GD_ * HD_];
__device__ float g_h   [S_ * HD_];
__device__ float g_htf [S_ * HD_];
__device__ float g_t2  [S_ * HD_];
__device__ float g_a1  [S_ * FF_];
__device__ float g_qkv [S_ * QKV_];
__device__ float g_vt  [GD_ * S_];
__device__ float g_ctx [S_ * GD_];
__device__ float g_sc  [G_ * S_ * S_];
__device__ float g_WqkvT[L_ * QKV_ * HD_];
__device__ float g_WoT  [L_ * HD_ * GD_];
__device__ float g_W1T  [L_ * FF_ * HD_];
__device__ float g_W2T  [L_ * HD_ * FF_];
__device__ float g_WheadT[(long long)V_ * HD_];

// ---------------- helpers ----------------
__device__ __forceinline__ uint32_t f2tf32(float f) {
    uint32_t r; asm("cvt.rna.tf32.f32 %0, %1;" : "=r"(r) : "f"(f)); return r;
}
__device__ __forceinline__ float rtf(float f) { return __uint_as_float(f2tf32(f)); }
__device__ __forceinline__ void cp16(uint32_t d, const float* g) {
    asm volatile("cp.async.cg.shared.global [%0], [%1], 16;\n" :: "r"(d), "l"(g));
}
__device__ __forceinline__ void ldx4(uint32_t* r, uint32_t addr) {
    asm volatile("ldmatrix.sync.aligned.m8n8.x4.shared.b16 {%0,%1,%2,%3}, [%4];"
                 : "=r"(r[0]), "=r"(r[1]), "=r"(r[2]), "=r"(r[3]) : "r"(addr));
}
__device__ __forceinline__ void mma_tf32(float c[4], const uint32_t a[4], const uint32_t b[2]) {
    asm volatile(
        "mma.sync.aligned.m16n8k8.row.col.f32.tf32.tf32.f32 "
        "{%0,%1,%2,%3}, {%4,%5,%6,%7}, {%8,%9}, {%0,%1,%2,%3};"
        : "+f"(c[0]), "+f"(c[1]), "+f"(c[2]), "+f"(c[3])
        : "r"(a[0]), "r"(a[1]), "r"(a[2]), "r"(a[3]), "r"(b[0]), "r"(b[1]));
}

// ---------------------------------------------------------------------------
// tf32 GEMM via ldmatrix-fed mma.sync.
//   C[M,N] = alpha * A[M,K] @ Bt[N,K]^T (+bias)
// GRID: x = M-tile (fastest -> co-resident CTAs share the same B tile via L2),
//       y = N-tile, z = batch/ksplit.
// Block 128 x BN_ x 32, 128 threads (2x2 warps of 64 x BN_/2).
// smem rows of 128B, XOR-swizzled; cp.async stores + ldmatrix reads
// conflict-free. flags: 1=relu, 2=tf32-round out, 4=atomicAdd
// ---------------------------------------------------------------------------
template<int BN_>
__global__ __launch_bounds__(128, 2) void gemm_ldm(
    const float* __restrict__ A, long long lda, long long sA,
    const float* __restrict__ Bt, long long ldb, long long sB,
    const float* __restrict__ bias,
    float* __restrict__ C, long long ldc, long long sC,
    int kchunks, long long kbz, float alpha, int flags)
{
    constexpr int NI = BN_ / 16;
    constexpr int ABYTES = 128 * 128;
    constexpr int STAGE  = ABYTES + BN_ * 128;
    extern __shared__ char dsm[];
    const uint32_t base = (uint32_t)__cvta_generic_to_shared(dsm);

    const long long bz = blockIdx.z;
    A  += bz * sA;
    Bt += bz * sB;
    C  += bz * sC;
    const long long kb = bz * kbz;

    const int tid  = threadIdx.x;
    const int lane = tid & 31;
    const int warp = tid >> 5;
    const int wm   = (warp & 1) * 64;
    const int wn   = (warp >> 1) * (BN_ / 2);
    const int gid  = lane >> 2;
    const int tg   = lane & 3;
    const int row0 = blockIdx.x * 128;      // M-tile on x (L2 B-sharing)
    const int col0 = blockIdx.y * BN_;      // N-tile on y

    const int rowA = lane & 15;
    const int acb  = (lane >> 4) & 1;
    const int rowB = (lane & 7) + ((lane >> 4) << 3);
    const int bcb  = (lane >> 3) & 1;
    const uint32_t amask = (uint32_t)(rowA & 7);
    const uint32_t bmask = (uint32_t)(rowB & 7);

    const int T = kchunks;

    auto load_chunk = [&](int i, int buf) {
        const long long k0 = kb + (long long)i * 32;
        const uint32_t sb = base + buf * STAGE;
#pragma unroll
        for (int p = 0; p < 8; p++) {
            int v = p * 128 + tid;
            int row = v >> 3, ch = v & 7;
            cp16(sb + (uint32_t)(row * 128 + ((ch ^ (row & 7)) << 4)),
                 A + (long long)(row0 + row) * lda + k0 + ch * 4);
        }
#pragma unroll
        for (int p = 0; p < BN_ / 16; p++) {
            int v = p * 128 + tid;
            int row = v >> 3, ch = v & 7;
            cp16(sb + (uint32_t)(ABYTES + row * 128 + ((ch ^ (row & 7)) << 4)),
                 Bt + (long long)(col0 + row) * ldb + k0 + ch * 4);
        }
        asm volatile("cp.async.commit_group;\n" ::);
    };

    float acc[4][NI][4];
#pragma unroll
    for (int mi = 0; mi < 4; mi++)
#pragma unroll
        for (int ni = 0; ni < NI; ni++)
#pragma unroll
            for (int c = 0; c < 4; c++) acc[mi][ni][c] = 0.f;

    load_chunk(0, 0);
    if (T > 1) load_chunk(1, 1);
    asm volatile("cp.async.wait_group 1;\n" ::);
    __syncthreads();

    for (int i = 0; i < T; i++) {
        const int buf = i & 1;
        const uint32_t Ab = base + buf * STAGE;
        const uint32_t Bb = Ab + ABYTES;

#pragma unroll
        for (int ks = 0; ks < 4; ks++) {
            const uint32_t ca = (uint32_t)(ks * 2 + acb);
            const uint32_t cb = (uint32_t)(ks * 2 + bcb);
            uint32_t afr[4][4];
#pragma unroll
            for (int mi = 0; mi < 4; mi++) {
                uint32_t r = (uint32_t)(wm + mi * 16 + rowA);
                ldx4(afr[mi], Ab + r * 128 + ((ca ^ amask) << 4));
            }
            uint32_t bfr[NI][2];
#pragma unroll
            for (int p = 0; p < NI / 2; p++) {
                uint32_t r = (uint32_t)(wn + p * 16 + rowB);
                uint32_t q[4];
                ldx4(q, Bb + r * 128 + ((cb ^ bmask) << 4));
                bfr[2 * p][0] = q[0]; bfr[2 * p][1] = q[1];
                bfr[2 * p + 1][0] = q[2]; bfr[2 * p + 1][1] = q[3];
            }
#pragma unroll
            for (int mi = 0; mi < 4; mi++)
#pragma unroll
                for (int ni = 0; ni < NI; ni++)
                    mma_tf32(acc[mi][ni], afr[mi], bfr[ni]);
        }

        if (i + 1 < T) {
            __syncthreads();
            if (i + 2 < T) {
                load_chunk(i + 2, buf);
                asm volatile("cp.async.wait_group 1;\n" ::);
            } else {
                asm volatile("cp.async.wait_group 0;\n" ::);
            }
            __syncthreads();
        }
    }

#pragma unroll
    for (int mi = 0; mi < 4; mi++) {
        int m0 = row0 + wm + mi * 16 + gid;
#pragma unroll
        for (int ni = 0; ni < NI; ni++) {
            int n = col0 + wn + ni * 8 + tg * 2;
            float v0 = alpha * acc[mi][ni][0];
            float v1 = alpha * acc[mi][ni][1];
            float v2 = alpha * acc[mi][ni][2];
            float v3 = alpha * acc[mi][ni][3];
            if (flags & 4) {
                atomicAdd(C + (long long)m0 * ldc + n, v0);
                atomicAdd(C + (long long)m0 * ldc + n + 1, v1);
                atomicAdd(C + (long long)(m0 + 8) * ldc + n, v2);
                atomicAdd(C + (long long)(m0 + 8) * ldc + n + 1, v3);
            } else {
                if (bias) {
                    float b0 = bias[n], b1 = bias[n + 1];
                    v0 += b0; v1 += b1; v2 += b0; v3 += b1;
                }
                if (flags & 1) {
                    v0 = fmaxf(v0, 0.f); v1 = fmaxf(v1, 0.f);
                    v2 = fmaxf(v2, 0.f); v3 = fmaxf(v3, 0.f);
                }
                if (flags & 2) { v0 = rtf(v0); v1 = rtf(v1); v2 = rtf(v2); v3 = rtf(v3); }
                *(float2*)(C + (long long)m0 * ldc + n)       = make_float2(v0, v1);
                *(float2*)(C + (long long)(m0 + 8) * ldc + n) = make_float2(v2, v3);
            }
        }
    }
}

// ---------------- elementwise kernels ----------------
__global__ __launch_bounds__(256) void softmax_kernel(float* __restrict__ Srows, int T)
{
    float* row = Srows + (long long)blockIdx.x * T;
    __shared__ float red[256];
    int tid = threadIdx.x;
    float m = -INFINITY;
    for (int i = tid; i < T; i += 256) m = fmaxf(m, row[i]);
    red[tid] = m; __syncthreads();
    for (int s = 128; s > 0; s >>= 1) { if (tid < s) red[tid] = fmaxf(red[tid], red[tid + s]); __syncthreads(); }
    m = red[0]; __syncthreads();
    float sum = 0.f;
    for (int i = tid; i < T; i += 256) { float e = expf(row[i] - m); row[i] = e; sum += e; }
    red[tid] = sum; __syncthreads();
    for (int s = 128; s > 0; s >>= 1) { if (tid < s) red[tid] += red[tid + s]; __syncthreads(); }
    float inv = 1.f / red[0];
    for (int i = tid; i < T; i += 256) row[i] = rtf(row[i] * inv);
}

__global__ __launch_bounds__(256) void ln_kernel(
    const float* __restrict__ X, const float* __restrict__ R,
    const float* __restrict__ g, const float* __restrict__ b,
    float* __restrict__ O, float* __restrict__ O2)
{
    long long off = (long long)blockIdx.x * HD_;
    __shared__ float red[256];
    int tid = threadIdx.x;
    float xv[8];
    float lsum = 0.f;
#pragma unroll
    for (int i = 0; i < 8; i++) {
        int c = tid + i * 256;
        float x = X[off + c];
        if (R) x += R[off + c];
        xv[i] = x; lsum += x;
    }
    red[tid] = lsum; __syncthreads();
    for (int s = 128; s > 0; s >>= 1) { if (tid < s) red[tid] += red[tid + s]; __syncthreads(); }
    float mean = red[0] * (1.f / HD_);
    __syncthreads();
    float lvar = 0.f;
#pragma unroll
    for (int i = 0; i < 8; i++) { float d = xv[i] - mean; lvar += d * d; }
    red[tid] = lvar; __syncthreads();
    for (int s = 128; s > 0; s >>= 1) { if (tid < s) red[tid] += red[tid + s]; __syncthreads(); }
    float inv = rsqrtf(red[0] * (1.f / HD_) + 1e-5f);
#pragma unroll
    for (int i = 0; i < 8; i++) {
        int c = tid + i * 256;
        float o = (xv[i] - mean) * inv * g[c] + b[c];
        O[off + c] = o;
        if (O2) O2[off + c] = rtf(o);
    }
}

__global__ __launch_bounds__(256) void embed_kernel(
    const int* __restrict__ ids, const float* __restrict__ tok,
    const float* __restrict__ pos, float* __restrict__ h, float* __restrict__ htf)
{
    long long idx = (long long)blockIdx.x * 256 + threadIdx.x;
    int c = (int)(idx & (HD_ - 1));
    int s = (int)(idx >> 11);
    float v = tok[(long long)ids[s] * HD_ + c] + pos[idx];
    h[idx] = v;
    htf[idx] = rtf(v);
}

__global__ __launch_bounds__(256) void init_bias_kernel(
    const float* __restrict__ b, float* __restrict__ o)
{
    long long idx = (long long)blockIdx.x * 256 + threadIdx.x;
    o[idx] = b[idx & (HD_ - 1)];
}

__global__ __launch_bounds__(256) void pack_wqkv_kernel(
    const float* __restrict__ Wq, const float* __restrict__ Wk,
    const float* __restrict__ Wv, float* __restrict__ Wqkv)
{
    long long idx = (long long)blockIdx.x * 256 + threadIdx.x;
    if (idx >= (long long)L_ * HD_ * QKV_) return;
    int col = (int)(idx % QKV_);
    long long rk = idx / QKV_;
    int k = (int)(rk & (HD_ - 1));
    int l = (int)(rk >> 11);
    float v;
    if (col < 256) {
        int gg = col >> 6, d = col & 63;
        const float* row = Wq + (((long long)l * HD_ + k) * HD_) + gg * (GS_ * D_) + d;
        float s = 0.f;
#pragma unroll
        for (int j = 0; j < GS_; j++) s += row[j * D_];
        v = s;
    } else if (col < 512) {
        v = Wk[((long long)l * HD_ + k) * GD_ + (col - 256)];
    } else {
        v = Wv[((long long)l * HD_ + k) * GD_ + (col - 512)];
    }
    Wqkv[idx] = v;
}

__global__ __launch_bounds__(256) void pack_bqkv_kernel(
    const float* __restrict__ bq, const float* __restrict__ bk,
    const float* __restrict__ bv, float* __restrict__ bqkv)
{
    int idx = blockIdx.x * 256 + threadIdx.x;
    if (idx >= L_ * QKV_) return;
    int col = idx % QKV_;
    int l = idx / QKV_;
    float v;
    if (col < 256) {
        int gg = col >> 6, d = col & 63;
        const float* row = bq + (long long)l * HD_ + gg * (GS_ * D_) + d;
        float s = 0.f;
#pragma unroll
        for (int j = 0; j < GS_; j++) s += row[j * D_];
        v = s;
    } else if (col < 512) v = bk[(long long)l * GD_ + (col - 256)];
    else v = bv[(long long)l * GD_ + (col - 512)];
    bqkv[idx] = v;
}

__global__ __launch_bounds__(256) void reduce_wo_kernel(
    const float* __restrict__ Wo, float* __restrict__ Wo_r)
{
    long long idx = (long long)blockIdx.x * 256 + threadIdx.x;
    int n = (int)(idx & (HD_ - 1));
    int gd = (int)((idx >> 11) & (GD_ - 1));
    int l = (int)(idx >> 19);
    int gg = gd >> 6, d = gd & 63;
    float s = 0.f;
#pragma unroll
    for (int j = 0; j < GS_; j++)
        s += Wo[(((long long)l * HD_) + gg * (GS_ * D_) + j * D_ + d) * HD_ + n];
    Wo_r[idx] = s;
}

// ---------------------------------------------------------------------------
// Vectorized transpose+round: dst[c][r] = rtf(src[r][c]).
// 32x32 tiles, float4 load + float4 store, conflict-free smem pattern.
// R, C multiples of 32; 256 threads = (tx 0..7) x (ty 0..31).
// ---------------------------------------------------------------------------
__global__ __launch_bounds__(256) void transpose_round_kernel(
    const float* __restrict__ src, float* __restrict__ dst, int R, int C)
{
    __shared__ float t[32][33];
    int r0 = blockIdx.y * 32, c0 = blockIdx.x * 32;
    int tx = threadIdx.x & 7, ty = threadIdx.x >> 3;
    float4 v = *(const float4*)(src + (long long)(r0 + ty) * C + c0 + tx * 4);
    t[ty][tx * 4 + 0] = v.x;
    t[ty][tx * 4 + 1] = v.y;
    t[ty][tx * 4 + 2] = v.z;
    t[ty][tx * 4 + 3] = v.w;
    __syncthreads();
    float4 o;
    o.x = rtf(t[tx * 4 + 0][ty]);
    o.y = rtf(t[tx * 4 + 1][ty]);
    o.z = rtf(t[tx * 4 + 2][ty]);
    o.w = rtf(t[tx * 4 + 3][ty]);
    *(float4*)(dst + (long long)(c0 + ty) * R + r0 + tx * 4) = o;
}

// vt[gd][t] = qkv[t][512+gd]
__global__ __launch_bounds__(256) void transpose_v_kernel(
    const float* __restrict__ qkv, float* __restrict__ vt)
{
    __shared__ float t[32][33];
    int c0 = blockIdx.x * 32;   // gd
    int r0 = blockIdx.y * 32;   // t
    int tx = threadIdx.x & 7, ty = threadIdx.x >> 3;
    float4 v = *(const float4*)(qkv + (long long)(r0 + ty) * QKV_ + 512 + c0 + tx * 4);
    t[ty][tx * 4 + 0] = v.x;
    t[ty][tx * 4 + 1] = v.y;
    t[ty][tx * 4 + 2] = v.z;
    t[ty][tx * 4 + 3] = v.w;
    __syncthreads();
    float4 o;
    o.x = t[tx * 4 + 0][ty];
    o.y = t[tx * 4 + 1][ty];
    o.z = t[tx * 4 + 2][ty];
    o.w = t[tx * 4 + 3][ty];
    *(float4*)(vt + (long long)(c0 + ty) * S_ + r0 + tx * 4) = o;
}

// ---------------- host ----------------
static const int SMEM_128 = 2 * (128 + 128) * 128;   // 65536
static const int SMEM_64  = 2 * (128 + 64) * 128;    // 49152

extern "C" void kernel_launch(void* const* d_in, const int* in_sizes, int n_in,
                              void* d_out, int out_size)
{
    const int*   ids     = (const int*)  d_in[0];
    const float* tok_emb = (const float*)d_in[1];
    const float* pos_emb = (const float*)d_in[2];
    const float* Wq  = (const float*)d_in[3];
    const float* bq  = (const float*)d_in[4];
    const float* Wk  = (const float*)d_in[5];
    const float* bk  = (const float*)d_in[6];
    const float* Wv  = (const float*)d_in[7];
    const float* bv  = (const float*)d_in[8];
    const float* Wo  = (const float*)d_in[9];
    const float* bo  = (const float*)d_in[10];
    const float* g1  = (const float*)d_in[11];
    const float* be1 = (const float*)d_in[12];
    const float* W1  = (const float*)d_in[13];
    const float* b1  = (const float*)d_in[14];
    const float* W2  = (const float*)d_in[15];
    const float* b2  = (const float*)d_in[16];
    const float* g2  = (const float*)d_in[17];
    const float* be2 = (const float*)d_in[18];
    const float* lnf_g = (const float*)d_in[19];
    const float* lnf_b = (const float*)d_in[20];
    const float* Whead = (const float*)d_in[21];
    float* out = (float*)d_out;

    cudaFuncSetAttribute(gemm_ldm<128>, cudaFuncAttributeMaxDynamicSharedMemorySize, SMEM_128);
    cudaFuncSetAttribute(gemm_ldm<64>,  cudaFuncAttributeMaxDynamicSharedMemorySize, SMEM_64);

    float *Wqkv, *bqkv, *Wo_r, *h, *htf, *t2, *a1, *qkv, *vt, *ctx, *sc;
    float *WqkvT, *WoT, *W1T, *W2T, *WheadT;
    cudaGetSymbolAddress((void**)&Wqkv, g_Wqkv);
    cudaGetSymbolAddress((void**)&bqkv, g_bqkv);
    cudaGetSymbolAddress((void**)&Wo_r, g_Wo_r);
    cudaGetSymbolAddress((void**)&h,    g_h);
    cudaGetSymbolAddress((void**)&htf,  g_htf);
    cudaGetSymbolAddress((void**)&t2,   g_t2);
    cudaGetSymbolAddress((void**)&a1,   g_a1);
    cudaGetSymbolAddress((void**)&qkv,  g_qkv);
    cudaGetSymbolAddress((void**)&vt,   g_vt);
    cudaGetSymbolAddress((void**)&ctx,  g_ctx);
    cudaGetSymbolAddress((void**)&sc,   g_sc);
    cudaGetSymbolAddress((void**)&WqkvT, g_WqkvT);
    cudaGetSymbolAddress((void**)&WoT,   g_WoT);
    cudaGetSymbolAddress((void**)&W1T,   g_W1T);
    cudaGetSymbolAddress((void**)&W2T,   g_W2T);
    cudaGetSymbolAddress((void**)&WheadT, g_WheadT);

    // ---- weight prep ----
    long long nwq = (long long)L_ * HD_ * QKV_;
    pack_wqkv_kernel<<<(int)((nwq + 255) / 256), 256>>>(Wq, Wk, Wv, Wqkv);
    pack_bqkv_kernel<<<(L_ * QKV_ + 255) / 256, 256>>>(bq, bk, bv, bqkv);
    reduce_wo_kernel<<<(L_ * GD_ * HD_) / 256, 256>>>(Wo, Wo_r);
    for (int l = 0; l < L_; l++) {
        transpose_round_kernel<<<dim3(QKV_ / 32, HD_ / 32), 256>>>(
            Wqkv + (long long)l * HD_ * QKV_, WqkvT + (long long)l * QKV_ * HD_, HD_, QKV_);
        transpose_round_kernel<<<dim3(HD_ / 32, GD_ / 32), 256>>>(
            Wo_r + (long long)l * GD_ * HD_, WoT + (long long)l * HD_ * GD_, GD_, HD_);
        transpose_round_kernel<<<dim3(FF_ / 32, HD_ / 32), 256>>>(
            W1 + (long long)l * HD_ * FF_, W1T + (long long)l * FF_ * HD_, HD_, FF_);
        transpose_round_kernel<<<dim3(HD_ / 32, FF_ / 32), 256>>>(
            W2 + (long long)l * FF_ * HD_, W2T + (long long)l * HD_ * FF_, FF_, HD_);
    }
    transpose_round_kernel<<<dim3(V_ / 32, HD_ / 32), 256>>>(Whead, WheadT, HD_, V_);

    embed_kernel<<<(S_ * HD_) / 256, 256>>>(ids, tok_emb, pos_emb, h, htf);

    for (int l = 0; l < L_; l++) {
        const float* WqkvT_l = WqkvT + (long long)l * QKV_ * HD_;
        const float* bqkv_l  = bqkv  + (long long)l * QKV_;
        const float* WoT_l   = WoT   + (long long)l * HD_ * GD_;
        const float* W1T_l   = W1T   + (long long)l * FF_ * HD_;
        const float* W2T_l   = W2T   + (long long)l * HD_ * FF_;

        // QKV projection
        gemm_ldm<128><<<dim3(S_ / 128, QKV_ / 128, 1), 128, SMEM_128>>>(
            htf, HD_, 0, WqkvT_l, HD_, 0, bqkv_l, qkv, QKV_, 0,
            HD_ / 32, 0, 1.f, 2);

        transpose_v_kernel<<<dim3(GD_ / 32, S_ / 32), 256>>>(qkv, vt);

        // scores[g] = 1/8 * Q_g @ K_g^T
        gemm_ldm<128><<<dim3(S_ / 128, S_ / 128, G_), 128, SMEM_128>>>(
            qkv, QKV_, 64, qkv + 256, QKV_, 64, nullptr,
            sc, S_, (long long)S_ * S_, 64 / 32, 0, 0.125f, 0);

        softmax_kernel<<<G_ * S_, 256>>>(sc, S_);

        // ctx[g] = attn_g @ V_g
        gemm_ldm<64><<<dim3(S_ / 128, 1, G_), 128, SMEM_64>>>(
            sc, S_, (long long)S_ * S_, vt, S_, (long long)D_ * S_, nullptr,
            ctx, GD_, 64, S_ / 32, 0, 1.f, 2);

        // attn_out = ctx @ Wo_r + bo ; h = LN(h + attn_out)
        gemm_ldm<128><<<dim3(S_ / 128, HD_ / 128, 1), 128, SMEM_128>>>(
            ctx, GD_, 0, WoT_l, GD_, 0, bo + (long long)l * HD_,
            t2, HD_, 0, GD_ / 32, 0, 1.f, 0);
        ln_kernel<<<S_, 256>>>(h, t2, g1 + (long long)l * HD_, be1 + (long long)l * HD_, h, htf);

        // FFN
        gemm_ldm<128><<<dim3(S_ / 128, FF_ / 128, 1), 128, SMEM_128>>>(
            htf, HD_, 0, W1T_l, HD_, 0, b1 + (long long)l * FF_,
            a1, FF_, 0, HD_ / 32, 0, 1.f, 1 | 2);
        init_bias_kernel<<<(S_ * HD_) / 256, 256>>>(b2 + (long long)l * HD_, t2);
        gemm_ldm<128><<<dim3(S_ / 128, HD_ / 128, 2), 128, SMEM_128>>>(
            a1, FF_, 0, W2T_l, FF_, 0, nullptr,
            t2, HD_, 0, FF_ / 32 / 2, (long long)(FF_ / 2), 1.f, 4);
        ln_kernel<<<S_, 256>>>(h, t2, g2 + (long long)l * HD_, be2 + (long long)l * HD_, h, htf);
    }

    // final LN + lm head
    ln_kernel<<<S_, 256>>>(h, nullptr, lnf_g, lnf_b, t2, a1);
    gemm_ldm<128><<<dim3(S_ / 128, V_ / 128, 1), 128, SMEM_128>>>(
        a1, HD_, 0, WheadT, HD_, 0, nullptr,
        out, V_, 0, HD_ / 32, 0, 1.f, 0);
}